// round 2
// baseline (speedup 1.0000x reference)
#include <cuda_runtime.h>

#define BB 8
#define LL 2048
#define DD 2048
#define NN 16
#define ROWS (BB*LL)
#define CS 32
#define CPB (LL/CS)
#define NCHUNK (ROWS/CS)

__device__ float g_delta[ROWS];
__device__ float g_Bt[ROWS*NN];
__device__ float g_Ct[ROWS*NN];
__device__ float g_Dt[ROWS];
__device__ float g_Ad[(size_t)ROWS*NN*NN];
__device__ float g_cP[NCHUNK*NN*NN];
__device__ float g_cq[NCHUNK*NN];
__device__ float g_cS[NCHUNK*NN];

// ---------------- K1: fused projections ----------------
__global__ __launch_bounds__(256) void k1_proj(
    const float* __restrict__ u,
    const float* __restrict__ Wb, const float* __restrict__ bb,
    const float* __restrict__ Wc, const float* __restrict__ bc,
    const float* __restrict__ Wd, const float* __restrict__ bd,
    const float* __restrict__ dp)
{
    __shared__ float su[64][68];
    __shared__ float sw[40][68];
    const int tid = threadIdx.x;
    const int ty = tid >> 3, tx = tid & 7;
    const int row0 = blockIdx.x * 64;

    float acc[2][5];
#pragma unroll
    for (int r = 0; r < 2; r++)
#pragma unroll
        for (int m = 0; m < 5; m++) acc[r][m] = 0.f;

    for (int k0 = 0; k0 < DD; k0 += 64) {
#pragma unroll
        for (int s4 = 0; s4 < 4; s4++) {
            int i = tid + 256 * s4;
            int r = i >> 4, cv = (i & 15) << 2;
            *reinterpret_cast<float4*>(&su[r][cv]) =
                *reinterpret_cast<const float4*>(u + (size_t)(row0 + r) * DD + k0 + cv);
        }
#pragma unroll
        for (int s4 = 0; s4 < 3; s4++) {
            int i = tid + 256 * s4;
            if (i < 640) {
                int r = i >> 4, cv = (i & 15) << 2;
                float4 v = make_float4(0.f, 0.f, 0.f, 0.f);
                const float* src = nullptr;
                if (r < 16)       src = Wb + (size_t)r * DD;
                else if (r < 32)  src = Wc + (size_t)(r - 16) * DD;
                else if (r == 32) src = Wd;
                else if (r == 33) src = dp;
                if (src) v = *reinterpret_cast<const float4*>(src + k0 + cv);
                *reinterpret_cast<float4*>(&sw[r][cv]) = v;
            }
        }
        __syncthreads();
#pragma unroll
        for (int kk = 0; kk < 64; kk += 4) {
            float4 a0 = *reinterpret_cast<float4*>(&su[ty][kk]);
            float4 a1 = *reinterpret_cast<float4*>(&su[ty + 32][kk]);
#pragma unroll
            for (int m = 0; m < 5; m++) {
                float4 w = *reinterpret_cast<float4*>(&sw[tx + 8 * m][kk]);
                acc[0][m] = fmaf(a0.x, w.x, acc[0][m]);
                acc[0][m] = fmaf(a0.y, w.y, acc[0][m]);
                acc[0][m] = fmaf(a0.z, w.z, acc[0][m]);
                acc[0][m] = fmaf(a0.w, w.w, acc[0][m]);
                acc[1][m] = fmaf(a1.x, w.x, acc[1][m]);
                acc[1][m] = fmaf(a1.y, w.y, acc[1][m]);
                acc[1][m] = fmaf(a1.z, w.z, acc[1][m]);
                acc[1][m] = fmaf(a1.w, w.w, acc[1][m]);
            }
        }
        __syncthreads();
    }
#pragma unroll
    for (int r = 0; r < 2; r++) {
        int row = row0 + ty + 32 * r;
#pragma unroll
        for (int m = 0; m < 5; m++) {
            int c = tx + 8 * m;
            float v = acc[r][m];
            if (c < 16)       g_Bt[row * NN + c] = v + bb[c];
            else if (c < 32)  g_Ct[row * NN + (c - 16)] = v + bc[c - 16];
            else if (c == 32) g_Dt[row] = v + bd[0];
            else if (c == 33) g_delta[row] = 1.f / (1.f + __expf(-v));
        }
    }
}

// ---------------- K2: batched expm ----------------
#define C3f 1.6666667e-1f
#define C4f 4.1666668e-2f
#define C5f 8.3333333e-3f
#define C6f 1.3888889e-3f
#define C7f 1.9841270e-4f
#define C8f 2.4801587e-5f
#define C9f 2.7557319e-6f

__device__ __forceinline__ void mm16(const float* __restrict__ A,
                                     const float* __restrict__ Bm,
                                     int i0, int j0, float c[4][4])
{
#pragma unroll
    for (int r = 0; r < 4; r++)
#pragma unroll
        for (int q = 0; q < 4; q++) c[r][q] = 0.f;
#pragma unroll
    for (int k = 0; k < 16; k++) {
        float b0 = Bm[k * 17 + j0 + 0];
        float b1 = Bm[k * 17 + j0 + 1];
        float b2 = Bm[k * 17 + j0 + 2];
        float b3 = Bm[k * 17 + j0 + 3];
#pragma unroll
        for (int r = 0; r < 4; r++) {
            float a = A[(i0 + r) * 17 + k];
            c[r][0] = fmaf(a, b0, c[r][0]);
            c[r][1] = fmaf(a, b1, c[r][1]);
            c[r][2] = fmaf(a, b2, c[r][2]);
            c[r][3] = fmaf(a, b3, c[r][3]);
        }
    }
}

__global__ __launch_bounds__(128) void k2_expm(const float* __restrict__ Ag)
{
    __shared__ float sm[8 * 1360];
    const int tid = threadIdx.x;
    const int mat = tid >> 4, q = tid & 15;
    const int i0 = (q >> 2) * 4, j0 = (q & 3) * 4;
    const int id0 = blockIdx.x * 8 + mat;
    const int t = id0 & (LL - 1);
    const float sd = 0.25f * g_delta[id0];

    float* Mb = sm + mat * 1360;
    float* M2b = Mb + 272;
    float* M3b = Mb + 544;
    float* T1 = Mb + 816;
    float* T2 = Mb + 1088;

    const float4* Ar = reinterpret_cast<const float4*>(Ag + (size_t)t * 256 + q * 16);
    float4 v0 = Ar[0], v1 = Ar[1], v2 = Ar[2], v3 = Ar[3];
    float* dst = Mb + q * 17;
    dst[0] = v0.x * sd;  dst[1] = v0.y * sd;  dst[2] = v0.z * sd;  dst[3] = v0.w * sd;
    dst[4] = v1.x * sd;  dst[5] = v1.y * sd;  dst[6] = v1.z * sd;  dst[7] = v1.w * sd;
    dst[8] = v2.x * sd;  dst[9] = v2.y * sd;  dst[10] = v2.z * sd; dst[11] = v2.w * sd;
    dst[12] = v3.x * sd; dst[13] = v3.y * sd; dst[14] = v3.z * sd; dst[15] = v3.w * sd;
    __syncwarp();

    float c[4][4];
    mm16(Mb, Mb, i0, j0, c);                 // M2
#pragma unroll
    for (int r = 0; r < 4; r++)
#pragma unroll
        for (int cc = 0; cc < 4; cc++) M2b[(i0 + r) * 17 + j0 + cc] = c[r][cc];
    __syncwarp();
    mm16(M2b, Mb, i0, j0, c);                // M3
#pragma unroll
    for (int r = 0; r < 4; r++)
#pragma unroll
        for (int cc = 0; cc < 4; cc++) M3b[(i0 + r) * 17 + j0 + cc] = c[r][cc];
    __syncwarp();
#pragma unroll
    for (int r = 0; r < 4; r++)              // T1 = b2
#pragma unroll
        for (int cc = 0; cc < 4; cc++) {
            int idx = (i0 + r) * 17 + j0 + cc;
            float val = C7f * Mb[idx] + C8f * M2b[idx] + C9f * M3b[idx];
            if (i0 + r == j0 + cc) val += C6f;
            T1[idx] = val;
        }
    __syncwarp();
    mm16(M3b, T1, i0, j0, c);                // T2 = M3*b2 + b1
#pragma unroll
    for (int r = 0; r < 4; r++)
#pragma unroll
        for (int cc = 0; cc < 4; cc++) {
            int idx = (i0 + r) * 17 + j0 + cc;
            float val = c[r][cc] + C4f * Mb[idx] + C5f * M2b[idx];
            if (i0 + r == j0 + cc) val += C3f;
            T2[idx] = val;
        }
    __syncwarp();
    mm16(M3b, T2, i0, j0, c);                // T1 = T9(M/4)
#pragma unroll
    for (int r = 0; r < 4; r++)
#pragma unroll
        for (int cc = 0; cc < 4; cc++) {
            int idx = (i0 + r) * 17 + j0 + cc;
            float val = c[r][cc] + Mb[idx] + 0.5f * M2b[idx];
            if (i0 + r == j0 + cc) val += 1.f;
            T1[idx] = val;
        }
    __syncwarp();
    mm16(T1, T1, i0, j0, c);                 // square 1
#pragma unroll
    for (int r = 0; r < 4; r++)
#pragma unroll
        for (int cc = 0; cc < 4; cc++) T2[(i0 + r) * 17 + j0 + cc] = c[r][cc];
    __syncwarp();
    mm16(T2, T2, i0, j0, c);                 // square 2 -> Ad
    size_t ob = (size_t)id0 * 256;
#pragma unroll
    for (int r = 0; r < 4; r++)
        *reinterpret_cast<float4*>(g_Ad + ob + (i0 + r) * 16 + j0) =
            make_float4(c[r][0], c[r][1], c[r][2], c[r][3]);
}

// ---------------- scan phase 1: per-chunk (P, q) ----------------
__global__ __launch_bounds__(256) void k_scan1()
{
    __shared__ float sm[8 * 880];
    const int warp = threadIdx.x >> 5, lane = threadIdx.x & 31;
    const int chunk = blockIdx.x * 8 + warp;
    float* base = sm + warp * 880;
    float* Ads = base;
    float* P0 = base + 272;
    float* P1 = base + 544;
    float* qb = base + 816;

    for (int i = lane; i < 272; i += 32) {
        int r = i / 17, col = i % 17;
        P0[i] = (col < 16 && r == col) ? 1.f : 0.f;
    }
    if (lane < 16) qb[lane] = 0.f;
    __syncwarp();

    const int i0 = (lane >> 2) * 2, j0 = (lane & 3) * 4;
    float* Pc = P0; float* Pn = P1;
    int qc = 0;
    size_t row = (size_t)chunk * CS;
    for (int tt = 0; tt < CS; tt++, row++) {
        const float4* src = reinterpret_cast<const float4*>(g_Ad + row * 256);
        float4 f0 = src[lane * 2], f1 = src[lane * 2 + 1];
        float* d = Ads + (lane >> 1) * 17 + (lane & 1) * 8;
        d[0] = f0.x; d[1] = f0.y; d[2] = f0.z; d[3] = f0.w;
        d[4] = f1.x; d[5] = f1.y; d[6] = f1.z; d[7] = f1.w;
        __syncwarp();
        float c0[4] = {0, 0, 0, 0}, c1[4] = {0, 0, 0, 0};
#pragma unroll
        for (int k = 0; k < 16; k++) {
            float a0 = Ads[i0 * 17 + k], a1 = Ads[(i0 + 1) * 17 + k];
            float b0 = Pc[k * 17 + j0 + 0];
            float b1 = Pc[k * 17 + j0 + 1];
            float b2 = Pc[k * 17 + j0 + 2];
            float b3 = Pc[k * 17 + j0 + 3];
            c0[0] = fmaf(a0, b0, c0[0]); c0[1] = fmaf(a0, b1, c0[1]);
            c0[2] = fmaf(a0, b2, c0[2]); c0[3] = fmaf(a0, b3, c0[3]);
            c1[0] = fmaf(a1, b0, c1[0]); c1[1] = fmaf(a1, b1, c1[1]);
            c1[2] = fmaf(a1, b2, c1[2]); c1[3] = fmaf(a1, b3, c1[3]);
        }
#pragma unroll
        for (int m = 0; m < 4; m++) {
            Pn[i0 * 17 + j0 + m] = c0[m];
            Pn[(i0 + 1) * 17 + j0 + m] = c1[m];
        }
        if (lane < 16) {
            float sn = g_Bt[row * NN + lane];
            const float* ar = Ads + lane * 17;
            const float* qo = qb + qc * 16;
#pragma unroll
            for (int k = 0; k < 16; k++) sn = fmaf(ar[k], qo[k], sn);
            qb[(qc ^ 1) * 16 + lane] = sn;
        }
        __syncwarp();
        float* tmp = Pc; Pc = Pn; Pn = tmp;
        qc ^= 1;
    }
#pragma unroll
    for (int m = 0; m < 4; m++) {
        g_cP[chunk * 256 + i0 * 16 + j0 + m] = Pc[i0 * 17 + j0 + m];
        g_cP[chunk * 256 + (i0 + 1) * 16 + j0 + m] = Pc[(i0 + 1) * 17 + j0 + m];
    }
    if (lane < 16) g_cq[chunk * 16 + lane] = qb[qc * 16 + lane];
}

// ---------------- scan phase 2: sequential over chunks ----------------
__global__ __launch_bounds__(256) void k_scan2()
{
    const int warp = threadIdx.x >> 5, lane = threadIdx.x & 31;
    if (lane >= 16) return;
    float s = 0.f;
    for (int ci = 0; ci < CPB; ci++) {
        int chunk = warp * CPB + ci;
        g_cS[chunk * 16 + lane] = s;
        const float4* Pr = reinterpret_cast<const float4*>(g_cP + chunk * 256 + lane * 16);
        float p[16];
        *reinterpret_cast<float4*>(&p[0])  = Pr[0];
        *reinterpret_cast<float4*>(&p[4])  = Pr[1];
        *reinterpret_cast<float4*>(&p[8])  = Pr[2];
        *reinterpret_cast<float4*>(&p[12]) = Pr[3];
        float sn = g_cq[chunk * 16 + lane];
#pragma unroll
        for (int k = 0; k < 16; k++)
            sn = fmaf(p[k], __shfl_sync(0xffffu, s, k, 16), sn);
        s = sn;
    }
}

// ---------------- scan phase 3: replay + output ----------------
__global__ __launch_bounds__(256) void k_scan3(float* __restrict__ y)
{
    const int warp = threadIdx.x >> 5, lane = threadIdx.x & 31;
    const int chunk = blockIdx.x * 8 + warp;
    if (lane >= 16) return;
    float s = g_cS[chunk * 16 + lane];
    size_t row = (size_t)chunk * CS;
    for (int tt = 0; tt < CS; tt++, row++) {
        const float4* Ar = reinterpret_cast<const float4*>(g_Ad + row * 256 + lane * 16);
        float a[16];
        *reinterpret_cast<float4*>(&a[0])  = Ar[0];
        *reinterpret_cast<float4*>(&a[4])  = Ar[1];
        *reinterpret_cast<float4*>(&a[8])  = Ar[2];
        *reinterpret_cast<float4*>(&a[12]) = Ar[3];
        float sn = g_Bt[row * NN + lane];
#pragma unroll
        for (int k = 0; k < 16; k++)
            sn = fmaf(a[k], __shfl_sync(0xffffu, s, k, 16), sn);
        s = sn;
        float v = g_Ct[row * NN + lane] * s;
#pragma unroll
        for (int o = 8; o > 0; o >>= 1) v += __shfl_xor_sync(0xffffu, v, o, 16);
        if (lane == 0) y[row] = v + g_Dt[row];
    }
}

extern "C" void kernel_launch(void* const* d_in, const int* in_sizes, int n_in,
                              void* d_out, int out_size)
{
    const float* u  = (const float*)d_in[0];
    const float* A  = (const float*)d_in[1];
    const float* dp = (const float*)d_in[2];
    const float* Wb = (const float*)d_in[3];
    const float* bb = (const float*)d_in[4];
    const float* Wc = (const float*)d_in[5];
    const float* bc = (const float*)d_in[6];
    const float* Wd = (const float*)d_in[7];
    const float* bd = (const float*)d_in[8];
    float* y = (float*)d_out;

    k1_proj<<<ROWS / 64, 256>>>(u, Wb, bb, Wc, bc, Wd, bd, dp);
    k2_expm<<<ROWS / 8, 128>>>(A);
    k_scan1<<<NCHUNK / 8, 256>>>();
    k_scan2<<<1, 256>>>();
    k_scan3<<<NCHUNK / 8, 256>>>(y);
}

// round 3
// speedup vs baseline: 1.0776x; 1.0776x over previous
#include <cuda_runtime.h>

#define BB 8
#define LL 2048
#define DD 2048
#define NN 16
#define ROWS (BB*LL)
#define CS 32
#define CPB (LL/CS)
#define NCHUNK (ROWS/CS)

__device__ float g_delta[ROWS];
__device__ float g_Bt[ROWS*NN];
__device__ float g_Ct[ROWS*NN];
__device__ float g_Dt[ROWS];
__device__ float g_Ad[(size_t)ROWS*NN*NN];
__device__ float g_cP[NCHUNK*NN*NN];
__device__ float g_cq[NCHUNK*NN];
__device__ float g_cS[NCHUNK*NN];

// ---------------- K1: fused projections ----------------
__global__ __launch_bounds__(256) void k1_proj(
    const float* __restrict__ u,
    const float* __restrict__ Wb, const float* __restrict__ bb,
    const float* __restrict__ Wc, const float* __restrict__ bc,
    const float* __restrict__ Wd, const float* __restrict__ bd,
    const float* __restrict__ dp)
{
    __shared__ float su[64][68];
    __shared__ float sw[40][68];
    const int tid = threadIdx.x;
    const int ty = tid >> 3, tx = tid & 7;
    const int row0 = blockIdx.x * 64;

    float acc[2][5];
#pragma unroll
    for (int r = 0; r < 2; r++)
#pragma unroll
        for (int m = 0; m < 5; m++) acc[r][m] = 0.f;

    for (int k0 = 0; k0 < DD; k0 += 64) {
#pragma unroll
        for (int s4 = 0; s4 < 4; s4++) {
            int i = tid + 256 * s4;
            int r = i >> 4, cv = (i & 15) << 2;
            *reinterpret_cast<float4*>(&su[r][cv]) =
                *reinterpret_cast<const float4*>(u + (size_t)(row0 + r) * DD + k0 + cv);
        }
#pragma unroll
        for (int s4 = 0; s4 < 3; s4++) {
            int i = tid + 256 * s4;
            if (i < 640) {
                int r = i >> 4, cv = (i & 15) << 2;
                float4 v = make_float4(0.f, 0.f, 0.f, 0.f);
                const float* src = nullptr;
                if (r < 16)       src = Wb + (size_t)r * DD;
                else if (r < 32)  src = Wc + (size_t)(r - 16) * DD;
                else if (r == 32) src = Wd;
                else if (r == 33) src = dp;
                if (src) v = *reinterpret_cast<const float4*>(src + k0 + cv);
                *reinterpret_cast<float4*>(&sw[r][cv]) = v;
            }
        }
        __syncthreads();
#pragma unroll
        for (int kk = 0; kk < 64; kk += 4) {
            float4 a0 = *reinterpret_cast<float4*>(&su[ty][kk]);
            float4 a1 = *reinterpret_cast<float4*>(&su[ty + 32][kk]);
#pragma unroll
            for (int m = 0; m < 5; m++) {
                float4 w = *reinterpret_cast<float4*>(&sw[tx + 8 * m][kk]);
                acc[0][m] = fmaf(a0.x, w.x, acc[0][m]);
                acc[0][m] = fmaf(a0.y, w.y, acc[0][m]);
                acc[0][m] = fmaf(a0.z, w.z, acc[0][m]);
                acc[0][m] = fmaf(a0.w, w.w, acc[0][m]);
                acc[1][m] = fmaf(a1.x, w.x, acc[1][m]);
                acc[1][m] = fmaf(a1.y, w.y, acc[1][m]);
                acc[1][m] = fmaf(a1.z, w.z, acc[1][m]);
                acc[1][m] = fmaf(a1.w, w.w, acc[1][m]);
            }
        }
        __syncthreads();
    }
#pragma unroll
    for (int r = 0; r < 2; r++) {
        int row = row0 + ty + 32 * r;
#pragma unroll
        for (int m = 0; m < 5; m++) {
            int c = tx + 8 * m;
            float v = acc[r][m];
            if (c < 16)       g_Bt[row * NN + c] = v + bb[c];
            else if (c < 32)  g_Ct[row * NN + (c - 16)] = v + bc[c - 16];
            else if (c == 32) g_Dt[row] = v + bd[0];
            else if (c == 33) g_delta[row] = 1.f / (1.f + __expf(-v));
        }
    }
}

// ---------------- K2: batched expm ----------------
#define C3f 1.6666667e-1f
#define C4f 4.1666668e-2f
#define C5f 8.3333333e-3f
#define C6f 1.3888889e-3f
#define C7f 1.9841270e-4f
#define C8f 2.4801587e-5f
#define C9f 2.7557319e-6f

__device__ __forceinline__ void mm16(const float* __restrict__ A,
                                     const float* __restrict__ Bm,
                                     int i0, int j0, float c[4][4])
{
#pragma unroll
    for (int r = 0; r < 4; r++)
#pragma unroll
        for (int q = 0; q < 4; q++) c[r][q] = 0.f;
#pragma unroll
    for (int k = 0; k < 16; k++) {
        float b0 = Bm[k * 17 + j0 + 0];
        float b1 = Bm[k * 17 + j0 + 1];
        float b2 = Bm[k * 17 + j0 + 2];
        float b3 = Bm[k * 17 + j0 + 3];
#pragma unroll
        for (int r = 0; r < 4; r++) {
            float a = A[(i0 + r) * 17 + k];
            c[r][0] = fmaf(a, b0, c[r][0]);
            c[r][1] = fmaf(a, b1, c[r][1]);
            c[r][2] = fmaf(a, b2, c[r][2]);
            c[r][3] = fmaf(a, b3, c[r][3]);
        }
    }
}

__global__ __launch_bounds__(128) void k2_expm(const float* __restrict__ Ag)
{
    __shared__ float sm[8 * 1360];
    const int tid = threadIdx.x;
    const int mat = tid >> 4, q = tid & 15;
    const int i0 = (q >> 2) * 4, j0 = (q & 3) * 4;
    const int id0 = blockIdx.x * 8 + mat;
    const int t = id0 & (LL - 1);
    const float sd = 0.25f * g_delta[id0];

    float* Mb = sm + mat * 1360;
    float* M2b = Mb + 272;
    float* M3b = Mb + 544;
    float* T1 = Mb + 816;
    float* T2 = Mb + 1088;

    const float4* Ar = reinterpret_cast<const float4*>(Ag + (size_t)t * 256 + q * 16);
    float4 v0 = Ar[0], v1 = Ar[1], v2 = Ar[2], v3 = Ar[3];
    float* dst = Mb + q * 17;
    dst[0] = v0.x * sd;  dst[1] = v0.y * sd;  dst[2] = v0.z * sd;  dst[3] = v0.w * sd;
    dst[4] = v1.x * sd;  dst[5] = v1.y * sd;  dst[6] = v1.z * sd;  dst[7] = v1.w * sd;
    dst[8] = v2.x * sd;  dst[9] = v2.y * sd;  dst[10] = v2.z * sd; dst[11] = v2.w * sd;
    dst[12] = v3.x * sd; dst[13] = v3.y * sd; dst[14] = v3.z * sd; dst[15] = v3.w * sd;
    __syncwarp();

    float c[4][4];
    mm16(Mb, Mb, i0, j0, c);                 // M2
#pragma unroll
    for (int r = 0; r < 4; r++)
#pragma unroll
        for (int cc = 0; cc < 4; cc++) M2b[(i0 + r) * 17 + j0 + cc] = c[r][cc];
    __syncwarp();
    mm16(M2b, Mb, i0, j0, c);                // M3
#pragma unroll
    for (int r = 0; r < 4; r++)
#pragma unroll
        for (int cc = 0; cc < 4; cc++) M3b[(i0 + r) * 17 + j0 + cc] = c[r][cc];
    __syncwarp();
#pragma unroll
    for (int r = 0; r < 4; r++)              // T1 = b2
#pragma unroll
        for (int cc = 0; cc < 4; cc++) {
            int idx = (i0 + r) * 17 + j0 + cc;
            float val = C7f * Mb[idx] + C8f * M2b[idx] + C9f * M3b[idx];
            if (i0 + r == j0 + cc) val += C6f;
            T1[idx] = val;
        }
    __syncwarp();
    mm16(M3b, T1, i0, j0, c);                // T2 = M3*b2 + b1
#pragma unroll
    for (int r = 0; r < 4; r++)
#pragma unroll
        for (int cc = 0; cc < 4; cc++) {
            int idx = (i0 + r) * 17 + j0 + cc;
            float val = c[r][cc] + C4f * Mb[idx] + C5f * M2b[idx];
            if (i0 + r == j0 + cc) val += C3f;
            T2[idx] = val;
        }
    __syncwarp();
    mm16(M3b, T2, i0, j0, c);                // T1 = T9(M/4)
#pragma unroll
    for (int r = 0; r < 4; r++)
#pragma unroll
        for (int cc = 0; cc < 4; cc++) {
            int idx = (i0 + r) * 17 + j0 + cc;
            float val = c[r][cc] + Mb[idx] + 0.5f * M2b[idx];
            if (i0 + r == j0 + cc) val += 1.f;
            T1[idx] = val;
        }
    __syncwarp();
    mm16(T1, T1, i0, j0, c);                 // square 1
#pragma unroll
    for (int r = 0; r < 4; r++)
#pragma unroll
        for (int cc = 0; cc < 4; cc++) T2[(i0 + r) * 17 + j0 + cc] = c[r][cc];
    __syncwarp();
    mm16(T2, T2, i0, j0, c);                 // square 2 -> Ad
    size_t ob = (size_t)id0 * 256;
#pragma unroll
    for (int r = 0; r < 4; r++)
        *reinterpret_cast<float4*>(g_Ad + ob + (i0 + r) * 16 + j0) =
            make_float4(c[r][0], c[r][1], c[r][2], c[r][3]);
}

// ---------------- scan phase 1: per-chunk (P, q), 4 warps/block, prefetch ----
__global__ __launch_bounds__(128) void k_scan1()
{
    __shared__ float sm[4 * 880];
    const int warp = threadIdx.x >> 5, lane = threadIdx.x & 31;
    const int chunk = blockIdx.x * 4 + warp;
    float* base = sm + warp * 880;
    float* Ads = base;
    float* P0 = base + 272;
    float* P1 = base + 544;
    float* qb = base + 816;

    for (int i = lane; i < 272; i += 32) {
        int r = i / 17, col = i % 17;
        P0[i] = (col < 16 && r == col) ? 1.f : 0.f;
    }
    if (lane < 16) qb[lane] = 0.f;

    const int i0 = (lane >> 2) * 2, j0 = (lane & 3) * 4;
    float* Pc = P0; float* Pn = P1;
    int qc = 0;
    size_t row = (size_t)chunk * CS;

    // preload step 0
    const float4* src = reinterpret_cast<const float4*>(g_Ad + row * 256);
    float4 f0 = src[lane * 2], f1 = src[lane * 2 + 1];
    float btv = (lane < 16) ? g_Bt[row * NN + lane] : 0.f;

    for (int tt = 0; tt < CS; tt++) {
        float* d = Ads + (lane >> 1) * 17 + (lane & 1) * 8;
        d[0] = f0.x; d[1] = f0.y; d[2] = f0.z; d[3] = f0.w;
        d[4] = f1.x; d[5] = f1.y; d[6] = f1.z; d[7] = f1.w;
        __syncwarp();
        // prefetch next step
        if (tt + 1 < CS) {
            const float4* nsrc = reinterpret_cast<const float4*>(g_Ad + (row + 1) * 256);
            f0 = nsrc[lane * 2]; f1 = nsrc[lane * 2 + 1];
        }
        float btn = (tt + 1 < CS && lane < 16) ? g_Bt[(row + 1) * NN + lane] : 0.f;

        float c0[4] = {0, 0, 0, 0}, c1[4] = {0, 0, 0, 0};
#pragma unroll
        for (int k = 0; k < 16; k++) {
            float a0 = Ads[i0 * 17 + k], a1 = Ads[(i0 + 1) * 17 + k];
            float b0 = Pc[k * 17 + j0 + 0];
            float b1 = Pc[k * 17 + j0 + 1];
            float b2 = Pc[k * 17 + j0 + 2];
            float b3 = Pc[k * 17 + j0 + 3];
            c0[0] = fmaf(a0, b0, c0[0]); c0[1] = fmaf(a0, b1, c0[1]);
            c0[2] = fmaf(a0, b2, c0[2]); c0[3] = fmaf(a0, b3, c0[3]);
            c1[0] = fmaf(a1, b0, c1[0]); c1[1] = fmaf(a1, b1, c1[1]);
            c1[2] = fmaf(a1, b2, c1[2]); c1[3] = fmaf(a1, b3, c1[3]);
        }
#pragma unroll
        for (int m = 0; m < 4; m++) {
            Pn[i0 * 17 + j0 + m] = c0[m];
            Pn[(i0 + 1) * 17 + j0 + m] = c1[m];
        }
        if (lane < 16) {
            float sn = btv;
            const float* ar = Ads + lane * 17;
            const float* qo = qb + qc * 16;
#pragma unroll
            for (int k = 0; k < 16; k++) sn = fmaf(ar[k], qo[k], sn);
            qb[(qc ^ 1) * 16 + lane] = sn;
        }
        __syncwarp();
        float* tmp = Pc; Pc = Pn; Pn = tmp;
        qc ^= 1;
        btv = btn;
        row++;
    }
#pragma unroll
    for (int m = 0; m < 4; m++) {
        g_cP[chunk * 256 + i0 * 16 + j0 + m] = Pc[i0 * 17 + j0 + m];
        g_cP[chunk * 256 + (i0 + 1) * 16 + j0 + m] = Pc[(i0 + 1) * 17 + j0 + m];
    }
    if (lane < 16) g_cq[chunk * 16 + lane] = qb[qc * 16 + lane];
}

// ---------------- scan phase 2: 1 block/batch, prefetch double-buffer -------
__global__ __launch_bounds__(32) void k_scan2()
{
    __shared__ float Ps[2][272];
    __shared__ float qs[2][16];
    const int b = blockIdx.x, lane = threadIdx.x;
    const int r = lane >> 1, c0 = (lane & 1) * 8;

    // prefetch chunk 0
    const float4* src = reinterpret_cast<const float4*>(g_cP + (size_t)(b * CPB) * 256);
    float4 pa = src[lane * 2], pb = src[lane * 2 + 1];
    float qn = (lane < 16) ? g_cq[(b * CPB) * 16 + lane] : 0.f;
    {
        float* d = &Ps[0][r * 17 + c0];
        d[0] = pa.x; d[1] = pa.y; d[2] = pa.z; d[3] = pa.w;
        d[4] = pb.x; d[5] = pb.y; d[6] = pb.z; d[7] = pb.w;
        if (lane < 16) qs[0][lane] = qn;
    }

    float s = 0.f;
    for (int ci = 0; ci < CPB; ci++) {
        int cur = ci & 1;
        if (ci + 1 < CPB) {   // issue next chunk's loads early
            const float4* ns = reinterpret_cast<const float4*>(
                g_cP + (size_t)(b * CPB + ci + 1) * 256);
            pa = ns[lane * 2]; pb = ns[lane * 2 + 1];
            if (lane < 16) qn = g_cq[(b * CPB + ci + 1) * 16 + lane];
        }
        __syncwarp();
        if (lane < 16) {
            g_cS[(b * CPB + ci) * 16 + lane] = s;
            const float* prow = &Ps[cur][lane * 17];
            float a0 = 0.f, a1 = 0.f, a2 = 0.f, a3 = 0.f;
#pragma unroll
            for (int k = 0; k < 4; k++) {
                a0 = fmaf(prow[k],      __shfl_sync(0xffffu, s, k,      16), a0);
                a1 = fmaf(prow[k + 4],  __shfl_sync(0xffffu, s, k + 4,  16), a1);
                a2 = fmaf(prow[k + 8],  __shfl_sync(0xffffu, s, k + 8,  16), a2);
                a3 = fmaf(prow[k + 12], __shfl_sync(0xffffu, s, k + 12, 16), a3);
            }
            s = ((a0 + a1) + (a2 + a3)) + qs[cur][lane];
        }
        __syncwarp();
        if (ci + 1 < CPB) {
            float* d = &Ps[cur ^ 1][r * 17 + c0];
            d[0] = pa.x; d[1] = pa.y; d[2] = pa.z; d[3] = pa.w;
            d[4] = pb.x; d[5] = pb.y; d[6] = pb.z; d[7] = pb.w;
            if (lane < 16) qs[cur ^ 1][lane] = qn;
        }
    }
}

// ---------------- scan phase 3: replay, 2 chunks per warp, prefetch ---------
__global__ __launch_bounds__(64) void k_scan3(float* __restrict__ y)
{
    const int warp = threadIdx.x >> 5, lane = threadIdx.x & 31;
    const int half = lane >> 4, l = lane & 15;
    const int chunk = blockIdx.x * 4 + warp * 2 + half;
    float s = g_cS[chunk * 16 + l];
    size_t row = (size_t)chunk * CS;

    // preload step 0
    const float4* Ar = reinterpret_cast<const float4*>(g_Ad + row * 256 + l * 16);
    float4 a0 = Ar[0], a1 = Ar[1], a2 = Ar[2], a3 = Ar[3];
    float btv = g_Bt[row * NN + l];
    float ctv = g_Ct[row * NN + l];
    float dtv = g_Dt[row];

    for (int tt = 0; tt < CS; tt++) {
        float4 n0, n1, n2, n3; float btn = 0.f, ctn = 0.f, dtn = 0.f;
        if (tt + 1 < CS) {
            const float4* Nr = reinterpret_cast<const float4*>(g_Ad + (row + 1) * 256 + l * 16);
            n0 = Nr[0]; n1 = Nr[1]; n2 = Nr[2]; n3 = Nr[3];
            btn = g_Bt[(row + 1) * NN + l];
            ctn = g_Ct[(row + 1) * NN + l];
            dtn = g_Dt[row + 1];
        }
        float x0 = 0.f, x1 = 0.f, x2 = 0.f, x3 = 0.f;
        x0 = fmaf(a0.x, __shfl_sync(0xffffffffu, s, 0, 16), x0);
        x0 = fmaf(a0.y, __shfl_sync(0xffffffffu, s, 1, 16), x0);
        x0 = fmaf(a0.z, __shfl_sync(0xffffffffu, s, 2, 16), x0);
        x0 = fmaf(a0.w, __shfl_sync(0xffffffffu, s, 3, 16), x0);
        x1 = fmaf(a1.x, __shfl_sync(0xffffffffu, s, 4, 16), x1);
        x1 = fmaf(a1.y, __shfl_sync(0xffffffffu, s, 5, 16), x1);
        x1 = fmaf(a1.z, __shfl_sync(0xffffffffu, s, 6, 16), x1);
        x1 = fmaf(a1.w, __shfl_sync(0xffffffffu, s, 7, 16), x1);
        x2 = fmaf(a2.x, __shfl_sync(0xffffffffu, s, 8, 16), x2);
        x2 = fmaf(a2.y, __shfl_sync(0xffffffffu, s, 9, 16), x2);
        x2 = fmaf(a2.z, __shfl_sync(0xffffffffu, s, 10, 16), x2);
        x2 = fmaf(a2.w, __shfl_sync(0xffffffffu, s, 11, 16), x2);
        x3 = fmaf(a3.x, __shfl_sync(0xffffffffu, s, 12, 16), x3);
        x3 = fmaf(a3.y, __shfl_sync(0xffffffffu, s, 13, 16), x3);
        x3 = fmaf(a3.z, __shfl_sync(0xffffffffu, s, 14, 16), x3);
        x3 = fmaf(a3.w, __shfl_sync(0xffffffffu, s, 15, 16), x3);
        s = ((x0 + x1) + (x2 + x3)) + btv;
        float v = ctv * s;
#pragma unroll
        for (int o = 8; o > 0; o >>= 1) v += __shfl_xor_sync(0xffffffffu, v, o, 16);
        if (l == 0) y[row] = v + dtv;
        a0 = n0; a1 = n1; a2 = n2; a3 = n3;
        btv = btn; ctv = ctn; dtv = dtn;
        row++;
    }
}

extern "C" void kernel_launch(void* const* d_in, const int* in_sizes, int n_in,
                              void* d_out, int out_size)
{
    const float* u  = (const float*)d_in[0];
    const float* A  = (const float*)d_in[1];
    const float* dp = (const float*)d_in[2];
    const float* Wb = (const float*)d_in[3];
    const float* bb = (const float*)d_in[4];
    const float* Wc = (const float*)d_in[5];
    const float* bc = (const float*)d_in[6];
    const float* Wd = (const float*)d_in[7];
    const float* bd = (const float*)d_in[8];
    float* y = (float*)d_out;

    k1_proj<<<ROWS / 64, 256>>>(u, Wb, bb, Wc, bc, Wd, bd, dp);
    k2_expm<<<ROWS / 8, 128>>>(A);
    k_scan1<<<NCHUNK / 4, 128>>>();
    k_scan2<<<BB, 32>>>();
    k_scan3<<<NCHUNK / 4, 64>>>(y);
}

// round 4
// speedup vs baseline: 1.1489x; 1.0661x over previous
#include <cuda_runtime.h>

#define BB 8
#define LL 2048
#define DD 2048
#define NN 16
#define ROWS (BB*LL)
#define CS 32
#define CPB (LL/CS)
#define NCHUNK (ROWS/CS)

__device__ float g_delta[ROWS];
__device__ float g_Bt[ROWS*NN];
__device__ float g_Ct[ROWS*NN];
__device__ float g_Dt[ROWS];
__device__ float g_Ad[(size_t)ROWS*NN*NN];
__device__ float g_cP[NCHUNK*NN*NN];
__device__ float g_cq[NCHUNK*NN];
__device__ float g_cS[NCHUNK*NN];

__device__ __forceinline__ unsigned s2u(const void* p) {
    unsigned a;
    asm("{ .reg .u64 t; cvta.to.shared.u64 t, %1; cvt.u32.u64 %0, t; }" : "=r"(a) : "l"(p));
    return a;
}
#define CP16(d, s) asm volatile("cp.async.ca.shared.global [%0], [%1], 16;\n" :: "r"(d), "l"(s))
#define CP4(d, s)  asm volatile("cp.async.ca.shared.global [%0], [%1], 4;\n"  :: "r"(d), "l"(s))
#define CPCOMMIT() asm volatile("cp.async.commit_group;\n")
#define CPWAIT1()  asm volatile("cp.async.wait_group 1;\n")

// ---------------- K1: fused projections ----------------
__global__ __launch_bounds__(256) void k1_proj(
    const float* __restrict__ u,
    const float* __restrict__ Wb, const float* __restrict__ bb,
    const float* __restrict__ Wc, const float* __restrict__ bc,
    const float* __restrict__ Wd, const float* __restrict__ bd,
    const float* __restrict__ dp)
{
    __shared__ float su[64][68];
    __shared__ float sw[40][68];
    const int tid = threadIdx.x;
    const int ty = tid >> 3, tx = tid & 7;
    const int row0 = blockIdx.x * 64;

    float acc[2][5];
#pragma unroll
    for (int r = 0; r < 2; r++)
#pragma unroll
        for (int m = 0; m < 5; m++) acc[r][m] = 0.f;

    for (int k0 = 0; k0 < DD; k0 += 64) {
#pragma unroll
        for (int s4 = 0; s4 < 4; s4++) {
            int i = tid + 256 * s4;
            int r = i >> 4, cv = (i & 15) << 2;
            *reinterpret_cast<float4*>(&su[r][cv]) =
                *reinterpret_cast<const float4*>(u + (size_t)(row0 + r) * DD + k0 + cv);
        }
#pragma unroll
        for (int s4 = 0; s4 < 3; s4++) {
            int i = tid + 256 * s4;
            if (i < 640) {
                int r = i >> 4, cv = (i & 15) << 2;
                float4 v = make_float4(0.f, 0.f, 0.f, 0.f);
                const float* src = nullptr;
                if (r < 16)       src = Wb + (size_t)r * DD;
                else if (r < 32)  src = Wc + (size_t)(r - 16) * DD;
                else if (r == 32) src = Wd;
                else if (r == 33) src = dp;
                if (src) v = *reinterpret_cast<const float4*>(src + k0 + cv);
                *reinterpret_cast<float4*>(&sw[r][cv]) = v;
            }
        }
        __syncthreads();
#pragma unroll
        for (int kk = 0; kk < 64; kk += 4) {
            float4 a0 = *reinterpret_cast<float4*>(&su[ty][kk]);
            float4 a1 = *reinterpret_cast<float4*>(&su[ty + 32][kk]);
#pragma unroll
            for (int m = 0; m < 5; m++) {
                float4 w = *reinterpret_cast<float4*>(&sw[tx + 8 * m][kk]);
                acc[0][m] = fmaf(a0.x, w.x, acc[0][m]);
                acc[0][m] = fmaf(a0.y, w.y, acc[0][m]);
                acc[0][m] = fmaf(a0.z, w.z, acc[0][m]);
                acc[0][m] = fmaf(a0.w, w.w, acc[0][m]);
                acc[1][m] = fmaf(a1.x, w.x, acc[1][m]);
                acc[1][m] = fmaf(a1.y, w.y, acc[1][m]);
                acc[1][m] = fmaf(a1.z, w.z, acc[1][m]);
                acc[1][m] = fmaf(a1.w, w.w, acc[1][m]);
            }
        }
        __syncthreads();
    }
#pragma unroll
    for (int r = 0; r < 2; r++) {
        int row = row0 + ty + 32 * r;
#pragma unroll
        for (int m = 0; m < 5; m++) {
            int c = tx + 8 * m;
            float v = acc[r][m];
            if (c < 16)       g_Bt[row * NN + c] = v + bb[c];
            else if (c < 32)  g_Ct[row * NN + (c - 16)] = v + bc[c - 16];
            else if (c == 32) g_Dt[row] = v + bd[0];
            else if (c == 33) g_delta[row] = 1.f / (1.f + __expf(-v));
        }
    }
}

// ---------------- K2: batched expm ----------------
#define C3f 1.6666667e-1f
#define C4f 4.1666668e-2f
#define C5f 8.3333333e-3f
#define C6f 1.3888889e-3f
#define C7f 1.9841270e-4f
#define C8f 2.4801587e-5f
#define C9f 2.7557319e-6f

__device__ __forceinline__ void mm16(const float* __restrict__ A,
                                     const float* __restrict__ Bm,
                                     int i0, int j0, float c[4][4])
{
#pragma unroll
    for (int r = 0; r < 4; r++)
#pragma unroll
        for (int q = 0; q < 4; q++) c[r][q] = 0.f;
#pragma unroll
    for (int k = 0; k < 16; k++) {
        float b0 = Bm[k * 17 + j0 + 0];
        float b1 = Bm[k * 17 + j0 + 1];
        float b2 = Bm[k * 17 + j0 + 2];
        float b3 = Bm[k * 17 + j0 + 3];
#pragma unroll
        for (int r = 0; r < 4; r++) {
            float a = A[(i0 + r) * 17 + k];
            c[r][0] = fmaf(a, b0, c[r][0]);
            c[r][1] = fmaf(a, b1, c[r][1]);
            c[r][2] = fmaf(a, b2, c[r][2]);
            c[r][3] = fmaf(a, b3, c[r][3]);
        }
    }
}

__global__ __launch_bounds__(128) void k2_expm(const float* __restrict__ Ag)
{
    __shared__ float sm[8 * 1360];
    const int tid = threadIdx.x;
    const int mat = tid >> 4, q = tid & 15;
    const int i0 = (q >> 2) * 4, j0 = (q & 3) * 4;
    const int id0 = blockIdx.x * 8 + mat;
    const int t = id0 & (LL - 1);
    const float sd = 0.25f * g_delta[id0];

    float* Mb = sm + mat * 1360;
    float* M2b = Mb + 272;
    float* M3b = Mb + 544;
    float* T1 = Mb + 816;
    float* T2 = Mb + 1088;

    const float4* Ar = reinterpret_cast<const float4*>(Ag + (size_t)t * 256 + q * 16);
    float4 v0 = Ar[0], v1 = Ar[1], v2 = Ar[2], v3 = Ar[3];
    float* dst = Mb + q * 17;
    dst[0] = v0.x * sd;  dst[1] = v0.y * sd;  dst[2] = v0.z * sd;  dst[3] = v0.w * sd;
    dst[4] = v1.x * sd;  dst[5] = v1.y * sd;  dst[6] = v1.z * sd;  dst[7] = v1.w * sd;
    dst[8] = v2.x * sd;  dst[9] = v2.y * sd;  dst[10] = v2.z * sd; dst[11] = v2.w * sd;
    dst[12] = v3.x * sd; dst[13] = v3.y * sd; dst[14] = v3.z * sd; dst[15] = v3.w * sd;
    __syncwarp();

    float c[4][4];
    mm16(Mb, Mb, i0, j0, c);
#pragma unroll
    for (int r = 0; r < 4; r++)
#pragma unroll
        for (int cc = 0; cc < 4; cc++) M2b[(i0 + r) * 17 + j0 + cc] = c[r][cc];
    __syncwarp();
    mm16(M2b, Mb, i0, j0, c);
#pragma unroll
    for (int r = 0; r < 4; r++)
#pragma unroll
        for (int cc = 0; cc < 4; cc++) M3b[(i0 + r) * 17 + j0 + cc] = c[r][cc];
    __syncwarp();
#pragma unroll
    for (int r = 0; r < 4; r++)
#pragma unroll
        for (int cc = 0; cc < 4; cc++) {
            int idx = (i0 + r) * 17 + j0 + cc;
            float val = C7f * Mb[idx] + C8f * M2b[idx] + C9f * M3b[idx];
            if (i0 + r == j0 + cc) val += C6f;
            T1[idx] = val;
        }
    __syncwarp();
    mm16(M3b, T1, i0, j0, c);
#pragma unroll
    for (int r = 0; r < 4; r++)
#pragma unroll
        for (int cc = 0; cc < 4; cc++) {
            int idx = (i0 + r) * 17 + j0 + cc;
            float val = c[r][cc] + C4f * Mb[idx] + C5f * M2b[idx];
            if (i0 + r == j0 + cc) val += C3f;
            T2[idx] = val;
        }
    __syncwarp();
    mm16(M3b, T2, i0, j0, c);
#pragma unroll
    for (int r = 0; r < 4; r++)
#pragma unroll
        for (int cc = 0; cc < 4; cc++) {
            int idx = (i0 + r) * 17 + j0 + cc;
            float val = c[r][cc] + Mb[idx] + 0.5f * M2b[idx];
            if (i0 + r == j0 + cc) val += 1.f;
            T1[idx] = val;
        }
    __syncwarp();
    mm16(T1, T1, i0, j0, c);
#pragma unroll
    for (int r = 0; r < 4; r++)
#pragma unroll
        for (int cc = 0; cc < 4; cc++) T2[(i0 + r) * 17 + j0 + cc] = c[r][cc];
    __syncwarp();
    mm16(T2, T2, i0, j0, c);
    size_t ob = (size_t)id0 * 256;
#pragma unroll
    for (int r = 0; r < 4; r++)
        *reinterpret_cast<float4*>(g_Ad + ob + (i0 + r) * 16 + j0) =
            make_float4(c[r][0], c[r][1], c[r][2], c[r][3]);
}

// ---------------- scan1: per-chunk (P,q), cp.async pipelined ----------------
// per-warp smem layout (floats): P0[272] P1[272] qb[32] AdB[2][336]
//   AdB buf: Ad 16 rows x stride 20 (=320), then Bt[16]
#define S1W 1248
__global__ __launch_bounds__(128) void k_scan1()
{
    __shared__ float sm[4 * S1W];
    const int warp = threadIdx.x >> 5, lane = threadIdx.x & 31;
    const int chunk = blockIdx.x * 4 + warp;
    float* base = sm + warp * S1W;
    float* P0 = base;
    float* P1 = base + 272;
    float* qb = base + 544;
    float* AdB = base + 576;

    for (int i = lane; i < 272; i += 32) {
        int r = i / 17, col = i % 17;
        P0[i] = (col < 16 && r == col) ? 1.f : 0.f;
    }
    if (lane < 16) qb[lane] = 0.f;

    const unsigned adu = s2u(AdB);
    const size_t row0 = (size_t)chunk * CS;

    // issue copies for step "rr" into buffer bi
    auto issue = [&](int bi, size_t rr) {
        unsigned d = adu + bi * 336 * 4;
#pragma unroll
        for (int j = 0; j < 2; j++) {
            int f = lane + 32 * j;           // 0..63 float4s of Ad row-major
            int r = f >> 2, c = (f & 3) << 2;
            CP16(d + (r * 20 + c) * 4, g_Ad + rr * 256 + f * 4);
        }
        if (lane < 4) CP16(d + (320 + lane * 4) * 4, g_Bt + rr * 16 + lane * 4);
    };

    issue(0, row0); CPCOMMIT();
    issue(1, row0 + 1); CPCOMMIT();

    const int i0 = (lane >> 2) * 2, j0 = (lane & 3) * 4;
    float* Pc = P0; float* Pn = P1;
    int qc = 0;
    for (int tt = 0; tt < CS; tt++) {
        CPWAIT1();
        __syncwarp();
        const float* Ab = AdB + (tt & 1) * 336;
        const float* Btb = Ab + 320;
        float c0[4] = {0, 0, 0, 0}, c1[4] = {0, 0, 0, 0};
#pragma unroll
        for (int k = 0; k < 16; k++) {
            float a0 = Ab[i0 * 20 + k], a1 = Ab[(i0 + 1) * 20 + k];
            float b0 = Pc[k * 17 + j0 + 0];
            float b1 = Pc[k * 17 + j0 + 1];
            float b2 = Pc[k * 17 + j0 + 2];
            float b3 = Pc[k * 17 + j0 + 3];
            c0[0] = fmaf(a0, b0, c0[0]); c0[1] = fmaf(a0, b1, c0[1]);
            c0[2] = fmaf(a0, b2, c0[2]); c0[3] = fmaf(a0, b3, c0[3]);
            c1[0] = fmaf(a1, b0, c1[0]); c1[1] = fmaf(a1, b1, c1[1]);
            c1[2] = fmaf(a1, b2, c1[2]); c1[3] = fmaf(a1, b3, c1[3]);
        }
#pragma unroll
        for (int m = 0; m < 4; m++) {
            Pn[i0 * 17 + j0 + m] = c0[m];
            Pn[(i0 + 1) * 17 + j0 + m] = c1[m];
        }
        if (lane < 16) {
            float sn = Btb[lane];
            const float* ar = Ab + lane * 20;
            const float* qo = qb + qc * 16;
#pragma unroll
            for (int k = 0; k < 16; k++) sn = fmaf(ar[k], qo[k], sn);
            qb[(qc ^ 1) * 16 + lane] = sn;
        }
        __syncwarp();
        if (tt + 2 < CS) issue(tt & 1, row0 + tt + 2);
        CPCOMMIT();
        float* tmp = Pc; Pc = Pn; Pn = tmp;
        qc ^= 1;
    }
#pragma unroll
    for (int m = 0; m < 4; m++) {
        g_cP[chunk * 256 + i0 * 16 + j0 + m] = Pc[i0 * 17 + j0 + m];
        g_cP[chunk * 256 + (i0 + 1) * 16 + j0 + m] = Pc[(i0 + 1) * 17 + j0 + m];
    }
    if (lane < 16) g_cq[chunk * 16 + lane] = qb[qc * 16 + lane];
}

// ---------------- scan2: bulk-stage 32 chunks to smem, warp0 scans ----------
__global__ __launch_bounds__(512) void k_scan2()
{
    __shared__ float Ps[32][272];   // 16 rows x stride 17 per chunk
    __shared__ float qs[32][16];
    const int tid = threadIdx.x;
    const int b = blockIdx.x;
    const int lane = tid & 31;
    float s = 0.f;

    for (int h = 0; h < 2; h++) {
        const int cbase = b * CPB + h * 32;
        for (int i = tid; i < 32 * 256; i += 512) {
            int ch = i >> 8, f = i & 255;
            int r = f >> 4, cc = f & 15;
            Ps[ch][r * 17 + cc] = g_cP[(size_t)(cbase + ch) * 256 + f];
        }
        {
            int ch = tid >> 4;
            if (ch < 32) qs[ch][tid & 15] = g_cq[(cbase + ch) * 16 + (tid & 15)];
        }
        __syncthreads();
        if (tid < 32 && lane < 16) {
            for (int ci = 0; ci < 32; ci++) {
                g_cS[(cbase + ci) * 16 + lane] = s;
                const float* prow = &Ps[ci][lane * 17];
                float a0 = 0.f, a1 = 0.f, a2 = 0.f, a3 = 0.f;
#pragma unroll
                for (int k = 0; k < 4; k++) {
                    a0 = fmaf(prow[k],      __shfl_sync(0xffffu, s, k,      16), a0);
                    a1 = fmaf(prow[k + 4],  __shfl_sync(0xffffu, s, k + 4,  16), a1);
                    a2 = fmaf(prow[k + 8],  __shfl_sync(0xffffu, s, k + 8,  16), a2);
                    a3 = fmaf(prow[k + 12], __shfl_sync(0xffffu, s, k + 12, 16), a3);
                }
                s = ((a0 + a1) + (a2 + a3)) + qs[ci][lane];
            }
        }
        __syncthreads();
    }
}

// ---------------- scan3: replay + output, cp.async pipelined ----------------
// per-warp: 2 bufs x 2 chunks x [Ad 320 (stride 20), Bt 16, Ct 16, Dt 4] = 356
#define S3C 356
#define S3B (2*S3C)
#define S3W (2*S3B)
__global__ __launch_bounds__(128) void k_scan3(float* __restrict__ y)
{
    __shared__ float sm[4 * S3W];
    const int warp = threadIdx.x >> 5, lane = threadIdx.x & 31;
    const int half = lane >> 4, l = lane & 15;
    const int chunk0 = blockIdx.x * 8 + warp * 2;
    float* base = sm + warp * S3W;
    const unsigned bu = s2u(base);
    const size_t r0 = (size_t)chunk0 * CS;       // chunk1 rows = r0 + CS + tt

    auto issue = [&](int bi, int tt) {
        unsigned d = bu + bi * S3B * 4;
        size_t ra = r0 + tt, rb = r0 + CS + tt;
#pragma unroll
        for (int j = 0; j < 2; j++) {
            int f = lane + 32 * j;
            int r = f >> 2, c = (f & 3) << 2;
            unsigned off = (r * 20 + c) * 4;
            CP16(d + off,               g_Ad + ra * 256 + f * 4);
            CP16(d + S3C * 4 + off,     g_Ad + rb * 256 + f * 4);
        }
        if (lane < 4)                 CP16(d + (320 + lane * 4) * 4,            g_Bt + ra * 16 + lane * 4);
        else if (lane < 8)            CP16(d + (S3C + 320 + (lane - 4) * 4) * 4, g_Bt + rb * 16 + (lane - 4) * 4);
        else if (lane < 12)           CP16(d + (336 + (lane - 8) * 4) * 4,      g_Ct + ra * 16 + (lane - 8) * 4);
        else if (lane < 16)           CP16(d + (S3C + 336 + (lane - 12) * 4) * 4, g_Ct + rb * 16 + (lane - 12) * 4);
        else if (lane == 16)          CP4(d + 352 * 4,          g_Dt + ra);
        else if (lane == 17)          CP4(d + (S3C + 352) * 4,  g_Dt + rb);
    };

    issue(0, 0); CPCOMMIT();
    issue(1, 1); CPCOMMIT();

    float s = g_cS[(chunk0 + half) * 16 + l];
    size_t row = r0 + half * CS;
    for (int tt = 0; tt < CS; tt++, row++) {
        CPWAIT1();
        __syncwarp();
        const float* cb = base + (tt & 1) * S3B + half * S3C;
        float4 a0 = *reinterpret_cast<const float4*>(cb + l * 20);
        float4 a1 = *reinterpret_cast<const float4*>(cb + l * 20 + 4);
        float4 a2 = *reinterpret_cast<const float4*>(cb + l * 20 + 8);
        float4 a3 = *reinterpret_cast<const float4*>(cb + l * 20 + 12);
        float btv = cb[320 + l], ctv = cb[336 + l], dtv = cb[352];

        float x0 = 0.f, x1 = 0.f, x2 = 0.f, x3 = 0.f;
        x0 = fmaf(a0.x, __shfl_sync(0xffffffffu, s, 0, 16), x0);
        x0 = fmaf(a0.y, __shfl_sync(0xffffffffu, s, 1, 16), x0);
        x0 = fmaf(a0.z, __shfl_sync(0xffffffffu, s, 2, 16), x0);
        x0 = fmaf(a0.w, __shfl_sync(0xffffffffu, s, 3, 16), x0);
        x1 = fmaf(a1.x, __shfl_sync(0xffffffffu, s, 4, 16), x1);
        x1 = fmaf(a1.y, __shfl_sync(0xffffffffu, s, 5, 16), x1);
        x1 = fmaf(a1.z, __shfl_sync(0xffffffffu, s, 6, 16), x1);
        x1 = fmaf(a1.w, __shfl_sync(0xffffffffu, s, 7, 16), x1);
        x2 = fmaf(a2.x, __shfl_sync(0xffffffffu, s, 8, 16), x2);
        x2 = fmaf(a2.y, __shfl_sync(0xffffffffu, s, 9, 16), x2);
        x2 = fmaf(a2.z, __shfl_sync(0xffffffffu, s, 10, 16), x2);
        x2 = fmaf(a2.w, __shfl_sync(0xffffffffu, s, 11, 16), x2);
        x3 = fmaf(a3.x, __shfl_sync(0xffffffffu, s, 12, 16), x3);
        x3 = fmaf(a3.y, __shfl_sync(0xffffffffu, s, 13, 16), x3);
        x3 = fmaf(a3.z, __shfl_sync(0xffffffffu, s, 14, 16), x3);
        x3 = fmaf(a3.w, __shfl_sync(0xffffffffu, s, 15, 16), x3);
        s = ((x0 + x1) + (x2 + x3)) + btv;
        float v = ctv * s;
#pragma unroll
        for (int o = 8; o > 0; o >>= 1) v += __shfl_xor_sync(0xffffffffu, v, o, 16);
        if (l == 0) y[row] = v + dtv;
        __syncwarp();
        if (tt + 2 < CS) issue(tt & 1, tt + 2);
        CPCOMMIT();
    }
}

extern "C" void kernel_launch(void* const* d_in, const int* in_sizes, int n_in,
                              void* d_out, int out_size)
{
    const float* u  = (const float*)d_in[0];
    const float* A  = (const float*)d_in[1];
    const float* dp = (const float*)d_in[2];
    const float* Wb = (const float*)d_in[3];
    const float* bb = (const float*)d_in[4];
    const float* Wc = (const float*)d_in[5];
    const float* bc = (const float*)d_in[6];
    const float* Wd = (const float*)d_in[7];
    const float* bd = (const float*)d_in[8];
    float* y = (float*)d_out;

    k1_proj<<<ROWS / 64, 256>>>(u, Wb, bb, Wc, bc, Wd, bd, dp);
    k2_expm<<<ROWS / 8, 128>>>(A);
    k_scan1<<<NCHUNK / 4, 128>>>();
    k_scan2<<<BB, 512>>>();
    k_scan3<<<NCHUNK / 8, 128>>>(y);
}

// round 7
// speedup vs baseline: 1.2265x; 1.0675x over previous
#include <cuda_runtime.h>

#define BB 8
#define LL 2048
#define DD 2048
#define NN 16
#define ROWS (BB*LL)
#define CS 32
#define CPB (LL/CS)
#define NCHUNK (ROWS/CS)

__device__ float g_delta[ROWS];
__device__ float g_Bt[ROWS*NN];
__device__ float g_Ct[ROWS*NN];
__device__ float g_Dt[ROWS];
__device__ float g_Ad[(size_t)ROWS*NN*NN];
__device__ float g_cP[NCHUNK*NN*NN];
__device__ float g_cq[NCHUNK*NN];
__device__ float g_cS[NCHUNK*NN];
__device__ float2 g_Wp[40*2048];     // hi/lo tf32 split of [Wb;Wc;Wd;dp;0..]

__device__ __forceinline__ unsigned s2u(const void* p) {
    unsigned a;
    asm("{ .reg .u64 t; cvta.to.shared.u64 t, %1; cvt.u32.u64 %0, t; }" : "=r"(a) : "l"(p));
    return a;
}
#define CP16(d, s) asm volatile("cp.async.ca.shared.global [%0], [%1], 16;\n" :: "r"(d), "l"(s))
#define CP4(d, s)  asm volatile("cp.async.ca.shared.global [%0], [%1], 4;\n"  :: "r"(d), "l"(s))
#define CPCOMMIT() asm volatile("cp.async.commit_group;\n")
#define CPWAIT1()  asm volatile("cp.async.wait_group 1;\n")

// cvt.rna.tf32.f32 requires a b32 destination register
__device__ __forceinline__ unsigned tf32b(float x) {
    unsigned y;
    asm("cvt.rna.tf32.f32 %0, %1;" : "=r"(y) : "f"(x));
    return y;
}
__device__ __forceinline__ float tf32f(float x) {
    return __uint_as_float(tf32b(x));
}
__device__ __forceinline__ void mma8(float c[4], unsigned a0, unsigned a1,
                                     unsigned a2, unsigned a3,
                                     unsigned b0, unsigned b1) {
    asm volatile(
        "mma.sync.aligned.m16n8k8.row.col.f32.tf32.tf32.f32 "
        "{%0,%1,%2,%3}, {%4,%5,%6,%7}, {%8,%9}, {%0,%1,%2,%3};"
        : "+f"(c[0]), "+f"(c[1]), "+f"(c[2]), "+f"(c[3])
        : "r"(a0), "r"(a1), "r"(a2), "r"(a3), "r"(b0), "r"(b1));
}

// ---------------- K0: split W into tf32 hi/lo pairs ----------------
__global__ __launch_bounds__(256) void k0_wsplit(
    const float* __restrict__ Wb, const float* __restrict__ Wc,
    const float* __restrict__ Wd, const float* __restrict__ dp)
{
    int idx = blockIdx.x * 256 + threadIdx.x;   // 0 .. 40*2048-1
    int r = idx >> 11, c = idx & 2047;
    float v = 0.f;
    if (r < 16)       v = Wb[r * DD + c];
    else if (r < 32)  v = Wc[(r - 16) * DD + c];
    else if (r == 32) v = Wd[c];
    else if (r == 33) v = dp[c];
    float h = tf32f(v);
    g_Wp[idx] = make_float2(h, tf32f(v - h));
}

// ---------------- K1: fused projections via tf32x3 tensor cores ------------
__global__ __launch_bounds__(128) void k1_proj(
    const float* __restrict__ u,
    const float* __restrict__ bb, const float* __restrict__ bc,
    const float* __restrict__ bd)
{
    __shared__ float2 sU[64 * 36];
    __shared__ float2 sW[40 * 36];
    const int tid = threadIdx.x;
    const int w = tid >> 5, lane = tid & 31;
    const int g = lane >> 2, t = lane & 3;
    const int row0 = blockIdx.x * 64;
    const int wrow = w * 16;

    float acc[5][4];
#pragma unroll
    for (int n = 0; n < 5; n++)
#pragma unroll
        for (int m = 0; m < 4; m++) acc[n][m] = 0.f;

    for (int kc = 0; kc < 64; kc++) {
        // stage u tile 64x32 as hi/lo pairs
#pragma unroll
        for (int j = 0; j < 4; j++) {
            int idx = tid + 128 * j;          // 0..511 float4s
            int r = idx >> 3, c4 = idx & 7;
            float4 v = *reinterpret_cast<const float4*>(
                u + (size_t)(row0 + r) * DD + kc * 32 + c4 * 4);
            float h0 = tf32f(v.x), h1 = tf32f(v.y), h2 = tf32f(v.z), h3 = tf32f(v.w);
            float2* d = &sU[r * 36 + c4 * 4];
            d[0] = make_float2(h0, tf32f(v.x - h0));
            d[1] = make_float2(h1, tf32f(v.y - h1));
            d[2] = make_float2(h2, tf32f(v.z - h2));
            d[3] = make_float2(h3, tf32f(v.w - h3));
        }
        // stage W pairs 40x32
#pragma unroll
        for (int j = 0; j < 5; j++) {
            int idx = tid + 128 * j;          // 0..639 float4s
            int r = idx >> 4, q = idx & 15;
            *reinterpret_cast<float4*>(&sW[r * 36 + q * 2]) =
                *reinterpret_cast<const float4*>(&g_Wp[r * 2048 + kc * 32 + q * 2]);
        }
        __syncthreads();
#pragma unroll
        for (int ks = 0; ks < 4; ks++) {
            int k = ks * 8;
            float2 a0p = sU[(wrow + g) * 36 + k + t];
            float2 a1p = sU[(wrow + g + 8) * 36 + k + t];
            float2 a2p = sU[(wrow + g) * 36 + k + t + 4];
            float2 a3p = sU[(wrow + g + 8) * 36 + k + t + 4];
            unsigned ah0 = __float_as_uint(a0p.x), al0 = __float_as_uint(a0p.y);
            unsigned ah1 = __float_as_uint(a1p.x), al1 = __float_as_uint(a1p.y);
            unsigned ah2 = __float_as_uint(a2p.x), al2 = __float_as_uint(a2p.y);
            unsigned ah3 = __float_as_uint(a3p.x), al3 = __float_as_uint(a3p.y);
#pragma unroll
            for (int nt = 0; nt < 5; nt++) {
                float2 b0p = sW[(nt * 8 + g) * 36 + k + t];
                float2 b1p = sW[(nt * 8 + g) * 36 + k + t + 4];
                unsigned bh0 = __float_as_uint(b0p.x), bl0 = __float_as_uint(b0p.y);
                unsigned bh1 = __float_as_uint(b1p.x), bl1 = __float_as_uint(b1p.y);
                mma8(acc[nt], ah0, ah1, ah2, ah3, bh0, bh1);
                mma8(acc[nt], ah0, ah1, ah2, ah3, bl0, bl1);
                mma8(acc[nt], al0, al1, al2, al3, bh0, bh1);
            }
        }
        __syncthreads();
    }
    // epilogue: c0:(g,2t) c1:(g,2t+1) c2:(g+8,2t) c3:(g+8,2t+1)
    const int rlo = row0 + wrow + g, rhi = rlo + 8;
#pragma unroll
    for (int nt = 0; nt < 5; nt++) {
#pragma unroll
        for (int m = 0; m < 4; m++) {
            int row = (m & 2) ? rhi : rlo;
            int col = nt * 8 + 2 * t + (m & 1);
            float v = acc[nt][m];
            if (col < 16)       g_Bt[row * NN + col] = v + bb[col];
            else if (col < 32)  g_Ct[row * NN + col - 16] = v + bc[col - 16];
            else if (col == 32) g_Dt[row] = v + bd[0];
            else if (col == 33) g_delta[row] = 1.f / (1.f + __expf(-v));
        }
    }
}

// ---------------- K2: batched expm (PS deg-9, 1 squaring, 5 matmuls) -------
#define C3f 1.6666667e-1f
#define C4f 4.1666668e-2f
#define C5f 8.3333333e-3f
#define C6f 1.3888889e-3f
#define C7f 1.9841270e-4f
#define C8f 2.4801587e-5f
#define C9f 2.7557319e-6f

__device__ __forceinline__ void mm16(const float* __restrict__ A,
                                     const float* __restrict__ Bm,
                                     int i0, int j0, float c[4][4])
{
#pragma unroll
    for (int r = 0; r < 4; r++)
#pragma unroll
        for (int q = 0; q < 4; q++) c[r][q] = 0.f;
#pragma unroll
    for (int k = 0; k < 16; k++) {
        float b0 = Bm[k * 17 + j0 + 0];
        float b1 = Bm[k * 17 + j0 + 1];
        float b2 = Bm[k * 17 + j0 + 2];
        float b3 = Bm[k * 17 + j0 + 3];
#pragma unroll
        for (int r = 0; r < 4; r++) {
            float a = A[(i0 + r) * 17 + k];
            c[r][0] = fmaf(a, b0, c[r][0]);
            c[r][1] = fmaf(a, b1, c[r][1]);
            c[r][2] = fmaf(a, b2, c[r][2]);
            c[r][3] = fmaf(a, b3, c[r][3]);
        }
    }
}

__global__ __launch_bounds__(128) void k2_expm(const float* __restrict__ Ag)
{
    __shared__ float sm[8 * 1360];
    const int tid = threadIdx.x;
    const int mat = tid >> 4, q = tid & 15;
    const int i0 = (q >> 2) * 4, j0 = (q & 3) * 4;
    const int id0 = blockIdx.x * 8 + mat;
    const int t = id0 & (LL - 1);
    const float sd = 0.5f * g_delta[id0];

    float* Mb = sm + mat * 1360;
    float* M2b = Mb + 272;
    float* M3b = Mb + 544;
    float* T1 = Mb + 816;
    float* T2 = Mb + 1088;

    const float4* Ar = reinterpret_cast<const float4*>(Ag + (size_t)t * 256 + q * 16);
    float4 v0 = Ar[0], v1 = Ar[1], v2 = Ar[2], v3 = Ar[3];
    float* dst = Mb + q * 17;
    dst[0] = v0.x * sd;  dst[1] = v0.y * sd;  dst[2] = v0.z * sd;  dst[3] = v0.w * sd;
    dst[4] = v1.x * sd;  dst[5] = v1.y * sd;  dst[6] = v1.z * sd;  dst[7] = v1.w * sd;
    dst[8] = v2.x * sd;  dst[9] = v2.y * sd;  dst[10] = v2.z * sd; dst[11] = v2.w * sd;
    dst[12] = v3.x * sd; dst[13] = v3.y * sd; dst[14] = v3.z * sd; dst[15] = v3.w * sd;
    __syncwarp();

    float c[4][4];
    mm16(Mb, Mb, i0, j0, c);                 // M2
#pragma unroll
    for (int r = 0; r < 4; r++)
#pragma unroll
        for (int cc = 0; cc < 4; cc++) M2b[(i0 + r) * 17 + j0 + cc] = c[r][cc];
    __syncwarp();
    mm16(M2b, Mb, i0, j0, c);                // M3
#pragma unroll
    for (int r = 0; r < 4; r++)
#pragma unroll
        for (int cc = 0; cc < 4; cc++) M3b[(i0 + r) * 17 + j0 + cc] = c[r][cc];
    __syncwarp();
#pragma unroll
    for (int r = 0; r < 4; r++)              // T1 = b2
#pragma unroll
        for (int cc = 0; cc < 4; cc++) {
            int idx = (i0 + r) * 17 + j0 + cc;
            float val = C7f * Mb[idx] + C8f * M2b[idx] + C9f * M3b[idx];
            if (i0 + r == j0 + cc) val += C6f;
            T1[idx] = val;
        }
    __syncwarp();
    mm16(M3b, T1, i0, j0, c);                // T2 = M3*b2 + b1
#pragma unroll
    for (int r = 0; r < 4; r++)
#pragma unroll
        for (int cc = 0; cc < 4; cc++) {
            int idx = (i0 + r) * 17 + j0 + cc;
            float val = c[r][cc] + C4f * Mb[idx] + C5f * M2b[idx];
            if (i0 + r == j0 + cc) val += C3f;
            T2[idx] = val;
        }
    __syncwarp();
    mm16(M3b, T2, i0, j0, c);                // T1 = T9(M/2)
#pragma unroll
    for (int r = 0; r < 4; r++)
#pragma unroll
        for (int cc = 0; cc < 4; cc++) {
            int idx = (i0 + r) * 17 + j0 + cc;
            float val = c[r][cc] + Mb[idx] + 0.5f * M2b[idx];
            if (i0 + r == j0 + cc) val += 1.f;
            T1[idx] = val;
        }
    __syncwarp();
    mm16(T1, T1, i0, j0, c);                 // single squaring -> Ad
    size_t ob = (size_t)id0 * 256;
#pragma unroll
    for (int r = 0; r < 4; r++)
        *reinterpret_cast<float4*>(g_Ad + ob + (i0 + r) * 16 + j0) =
            make_float4(c[r][0], c[r][1], c[r][2], c[r][3]);
}

// ---------------- scan1: per-chunk (P,q), cp.async pipelined ----------------
#define S1W 1248
__global__ __launch_bounds__(128) void k_scan1()
{
    __shared__ float sm[4 * S1W];
    const int warp = threadIdx.x >> 5, lane = threadIdx.x & 31;
    const int chunk = blockIdx.x * 4 + warp;
    float* base = sm + warp * S1W;
    float* P0 = base;
    float* P1 = base + 272;
    float* qb = base + 544;
    float* AdB = base + 576;

    for (int i = lane; i < 272; i += 32) {
        int r = i / 17, col = i % 17;
        P0[i] = (col < 16 && r == col) ? 1.f : 0.f;
    }
    if (lane < 16) qb[lane] = 0.f;

    const unsigned adu = s2u(AdB);
    const size_t row0 = (size_t)chunk * CS;

    auto issue = [&](int bi, size_t rr) {
        unsigned d = adu + bi * 336 * 4;
#pragma unroll
        for (int j = 0; j < 2; j++) {
            int f = lane + 32 * j;
            int r = f >> 2, c = (f & 3) << 2;
            CP16(d + (r * 20 + c) * 4, g_Ad + rr * 256 + f * 4);
        }
        if (lane < 4) CP16(d + (320 + lane * 4) * 4, g_Bt + rr * 16 + lane * 4);
    };

    issue(0, row0); CPCOMMIT();
    issue(1, row0 + 1); CPCOMMIT();

    const int i0 = (lane >> 2) * 2, j0 = (lane & 3) * 4;
    float* Pc = P0; float* Pn = P1;
    int qc = 0;
    for (int tt = 0; tt < CS; tt++) {
        CPWAIT1();
        __syncwarp();
        const float* Ab = AdB + (tt & 1) * 336;
        const float* Btb = Ab + 320;
        float c0[4] = {0, 0, 0, 0}, c1[4] = {0, 0, 0, 0};
#pragma unroll
        for (int k = 0; k < 16; k++) {
            float a0 = Ab[i0 * 20 + k], a1 = Ab[(i0 + 1) * 20 + k];
            float b0 = Pc[k * 17 + j0 + 0];
            float b1 = Pc[k * 17 + j0 + 1];
            float b2 = Pc[k * 17 + j0 + 2];
            float b3 = Pc[k * 17 + j0 + 3];
            c0[0] = fmaf(a0, b0, c0[0]); c0[1] = fmaf(a0, b1, c0[1]);
            c0[2] = fmaf(a0, b2, c0[2]); c0[3] = fmaf(a0, b3, c0[3]);
            c1[0] = fmaf(a1, b0, c1[0]); c1[1] = fmaf(a1, b1, c1[1]);
            c1[2] = fmaf(a1, b2, c1[2]); c1[3] = fmaf(a1, b3, c1[3]);
        }
#pragma unroll
        for (int m = 0; m < 4; m++) {
            Pn[i0 * 17 + j0 + m] = c0[m];
            Pn[(i0 + 1) * 17 + j0 + m] = c1[m];
        }
        if (lane < 16) {
            float sn = Btb[lane];
            const float* ar = Ab + lane * 20;
            const float* qo = qb + qc * 16;
#pragma unroll
            for (int k = 0; k < 16; k++) sn = fmaf(ar[k], qo[k], sn);
            qb[(qc ^ 1) * 16 + lane] = sn;
        }
        __syncwarp();
        if (tt + 2 < CS) issue(tt & 1, row0 + tt + 2);
        CPCOMMIT();
        float* tmp = Pc; Pc = Pn; Pn = tmp;
        qc ^= 1;
    }
#pragma unroll
    for (int m = 0; m < 4; m++) {
        g_cP[chunk * 256 + i0 * 16 + j0 + m] = Pc[i0 * 17 + j0 + m];
        g_cP[chunk * 256 + (i0 + 1) * 16 + j0 + m] = Pc[(i0 + 1) * 17 + j0 + m];
    }
    if (lane < 16) g_cq[chunk * 16 + lane] = qb[qc * 16 + lane];
}

// ---------------- scan2: bulk-stage 32 chunks to smem, warp0 scans ----------
__global__ __launch_bounds__(512) void k_scan2()
{
    __shared__ float Ps[32][272];
    __shared__ float qs[32][16];
    const int tid = threadIdx.x;
    const int b = blockIdx.x;
    const int lane = tid & 31;
    float s = 0.f;

    for (int h = 0; h < 2; h++) {
        const int cbase = b * CPB + h * 32;
        for (int i = tid; i < 32 * 256; i += 512) {
            int ch = i >> 8, f = i & 255;
            int r = f >> 4, cc = f & 15;
            Ps[ch][r * 17 + cc] = g_cP[(size_t)(cbase + ch) * 256 + f];
        }
        {
            int ch = tid >> 4;
            if (ch < 32) qs[ch][tid & 15] = g_cq[(cbase + ch) * 16 + (tid & 15)];
        }
        __syncthreads();
        if (tid < 32 && lane < 16) {
            for (int ci = 0; ci < 32; ci++) {
                g_cS[(cbase + ci) * 16 + lane] = s;
                const float* prow = &Ps[ci][lane * 17];
                float a0 = 0.f, a1 = 0.f, a2 = 0.f, a3 = 0.f;
#pragma unroll
                for (int k = 0; k < 4; k++) {
                    a0 = fmaf(prow[k],      __shfl_sync(0xffffu, s, k,      16), a0);
                    a1 = fmaf(prow[k + 4],  __shfl_sync(0xffffu, s, k + 4,  16), a1);
                    a2 = fmaf(prow[k + 8],  __shfl_sync(0xffffu, s, k + 8,  16), a2);
                    a3 = fmaf(prow[k + 12], __shfl_sync(0xffffu, s, k + 12, 16), a3);
                }
                s = ((a0 + a1) + (a2 + a3)) + qs[ci][lane];
            }
        }
        __syncthreads();
    }
}

// ---------------- scan3: replay + output, cp.async pipelined ----------------
#define S3C 356
#define S3B (2*S3C)
#define S3W (2*S3B)
__global__ __launch_bounds__(128) void k_scan3(float* __restrict__ y)
{
    __shared__ float sm[4 * S3W];
    const int warp = threadIdx.x >> 5, lane = threadIdx.x & 31;
    const int half = lane >> 4, l = lane & 15;
    const int chunk0 = blockIdx.x * 8 + warp * 2;
    float* base = sm + warp * S3W;
    const unsigned bu = s2u(base);
    const size_t r0 = (size_t)chunk0 * CS;

    auto issue = [&](int bi, int tt) {
        unsigned d = bu + bi * S3B * 4;
        size_t ra = r0 + tt, rb = r0 + CS + tt;
#pragma unroll
        for (int j = 0; j < 2; j++) {
            int f = lane + 32 * j;
            int r = f >> 2, c = (f & 3) << 2;
            unsigned off = (r * 20 + c) * 4;
            CP16(d + off,           g_Ad + ra * 256 + f * 4);
            CP16(d + S3C * 4 + off, g_Ad + rb * 256 + f * 4);
        }
        if (lane < 4)       CP16(d + (320 + lane * 4) * 4,              g_Bt + ra * 16 + lane * 4);
        else if (lane < 8)  CP16(d + (S3C + 320 + (lane - 4) * 4) * 4,  g_Bt + rb * 16 + (lane - 4) * 4);
        else if (lane < 12) CP16(d + (336 + (lane - 8) * 4) * 4,        g_Ct + ra * 16 + (lane - 8) * 4);
        else if (lane < 16) CP16(d + (S3C + 336 + (lane - 12) * 4) * 4, g_Ct + rb * 16 + (lane - 12) * 4);
        else if (lane == 16) CP4(d + 352 * 4,         g_Dt + ra);
        else if (lane == 17) CP4(d + (S3C + 352) * 4, g_Dt + rb);
    };

    issue(0, 0); CPCOMMIT();
    issue(1, 1); CPCOMMIT();

    float s = g_cS[(chunk0 + half) * 16 + l];
    size_t row = r0 + half * CS;
    for (int tt = 0; tt < CS; tt++, row++) {
        CPWAIT1();
        __syncwarp();
        const float* cb = base + (tt & 1) * S3B + half * S3C;
        float4 a0 = *reinterpret_cast<const float4*>(cb + l * 20);
        float4 a1 = *reinterpret_cast<const float4*>(cb + l * 20 + 4);
        float4 a2 = *reinterpret_cast<const float4*>(cb + l * 20 + 8);
        float4 a3 = *reinterpret_cast<const float4*>(cb + l * 20 + 12);
        float btv = cb[320 + l], ctv = cb[336 + l], dtv = cb[352];

        float x0 = 0.f, x1 = 0.f, x2 = 0.f, x3 = 0.f;
        x0 = fmaf(a0.x, __shfl_sync(0xffffffffu, s, 0, 16), x0);
        x0 = fmaf(a0.y, __shfl_sync(0xffffffffu, s, 1, 16), x0);
        x0 = fmaf(a0.z, __shfl_sync(0xffffffffu, s, 2, 16), x0);
        x0 = fmaf(a0.w, __shfl_sync(0xffffffffu, s, 3, 16), x0);
        x1 = fmaf(a1.x, __shfl_sync(0xffffffffu, s, 4, 16), x1);
        x1 = fmaf(a1.y, __shfl_sync(0xffffffffu, s, 5, 16), x1);
        x1 = fmaf(a1.z, __shfl_sync(0xffffffffu, s, 6, 16), x1);
        x1 = fmaf(a1.w, __shfl_sync(0xffffffffu, s, 7, 16), x1);
        x2 = fmaf(a2.x, __shfl_sync(0xffffffffu, s, 8, 16), x2);
        x2 = fmaf(a2.y, __shfl_sync(0xffffffffu, s, 9, 16), x2);
        x2 = fmaf(a2.z, __shfl_sync(0xffffffffu, s, 10, 16), x2);
        x2 = fmaf(a2.w, __shfl_sync(0xffffffffu, s, 11, 16), x2);
        x3 = fmaf(a3.x, __shfl_sync(0xffffffffu, s, 12, 16), x3);
        x3 = fmaf(a3.y, __shfl_sync(0xffffffffu, s, 13, 16), x3);
        x3 = fmaf(a3.z, __shfl_sync(0xffffffffu, s, 14, 16), x3);
        x3 = fmaf(a3.w, __shfl_sync(0xffffffffu, s, 15, 16), x3);
        s = ((x0 + x1) + (x2 + x3)) + btv;
        float v = ctv * s;
#pragma unroll
        for (int o = 8; o > 0; o >>= 1) v += __shfl_xor_sync(0xffffffffu, v, o, 16);
        if (l == 0) y[row] = v + dtv;
        __syncwarp();
        if (tt + 2 < CS) issue(tt & 1, tt + 2);
        CPCOMMIT();
    }
}

extern "C" void kernel_launch(void* const* d_in, const int* in_sizes, int n_in,
                              void* d_out, int out_size)
{
    const float* u  = (const float*)d_in[0];
    const float* A  = (const float*)d_in[1];
    const float* dp = (const float*)d_in[2];
    const float* Wb = (const float*)d_in[3];
    const float* bb = (const float*)d_in[4];
    const float* Wc = (const float*)d_in[5];
    const float* bc = (const float*)d_in[6];
    const float* Wd = (const float*)d_in[7];
    const float* bd = (const float*)d_in[8];
    float* y = (float*)d_out;

    k0_wsplit<<<(40 * 2048) / 256, 256>>>(Wb, Wc, Wd, dp);
    k1_proj<<<ROWS / 64, 128>>>(u, bb, bc, bd);
    k2_expm<<<ROWS / 8, 128>>>(A);
    k_scan1<<<NCHUNK / 4, 128>>>();
    k_scan2<<<BB, 512>>>();
    k_scan3<<<NCHUNK / 8, 128>>>(y);
}

// round 11
// speedup vs baseline: 1.5979x; 1.3028x over previous
#include <cuda_runtime.h>

#define BB 8
#define LL 2048
#define DD 2048
#define NN 16
#define ROWS (BB*LL)
#define CS 32
#define CPB (LL/CS)
#define NCHUNK (ROWS/CS)

__device__ float g_delta[ROWS];
__device__ float g_Bt[ROWS*NN];
__device__ float g_Ct[ROWS*NN];
__device__ float g_Dt[ROWS];
__device__ float g_Ad[(size_t)ROWS*NN*NN];
__device__ float g_cP[NCHUNK*NN*NN];
__device__ float g_cq[NCHUNK*NN];
__device__ float g_cS[NCHUNK*NN];
__device__ __align__(16) float2 g_Wp[40*2048];  // hi/lo tf32 split of [Wb;Wc;Wd;dp;0..]

__device__ __forceinline__ unsigned s2u(const void* p) {
    unsigned a;
    asm("{ .reg .u64 t; cvta.to.shared.u64 t, %1; cvt.u32.u64 %0, t; }" : "=r"(a) : "l"(p));
    return a;
}
#define CP16(d, s) asm volatile("cp.async.ca.shared.global [%0], [%1], 16;\n" :: "r"(d), "l"(s))
#define CP4(d, s)  asm volatile("cp.async.ca.shared.global [%0], [%1], 4;\n"  :: "r"(d), "l"(s))
#define CPCOMMIT() asm volatile("cp.async.commit_group;\n")
#define CPWAIT1()  asm volatile("cp.async.wait_group 1;\n")

// cvt.rna.tf32.f32 requires a b32 destination register
__device__ __forceinline__ unsigned tf32b(float x) {
    unsigned y;
    asm("cvt.rna.tf32.f32 %0, %1;" : "=r"(y) : "f"(x));
    return y;
}
__device__ __forceinline__ float tf32f(float x) {
    return __uint_as_float(tf32b(x));
}
__device__ __forceinline__ void mma8(float c[4], unsigned a0, unsigned a1,
                                     unsigned a2, unsigned a3,
                                     unsigned b0, unsigned b1) {
    asm volatile(
        "mma.sync.aligned.m16n8k8.row.col.f32.tf32.tf32.f32 "
        "{%0,%1,%2,%3}, {%4,%5,%6,%7}, {%8,%9}, {%0,%1,%2,%3};"
        : "+f"(c[0]), "+f"(c[1]), "+f"(c[2]), "+f"(c[3])
        : "r"(a0), "r"(a1), "r"(a2), "r"(a3), "r"(b0), "r"(b1));
}

// ---------------- K0: split W into tf32 hi/lo pairs ----------------
__global__ __launch_bounds__(256) void k0_wsplit(
    const float* __restrict__ Wb, const float* __restrict__ Wc,
    const float* __restrict__ Wd, const float* __restrict__ dp)
{
    int idx = blockIdx.x * 256 + threadIdx.x;   // 0 .. 40*2048-1
    int r = idx >> 11, c = idx & 2047;
    float v = 0.f;
    if (r < 16)       v = Wb[r * DD + c];
    else if (r < 32)  v = Wc[(r - 16) * DD + c];
    else if (r == 32) v = Wd[c];
    else if (r == 33) v = dp[c];
    float h = tf32f(v);
    g_Wp[idx] = make_float2(h, tf32f(v - h));
}

// ---------------- K1: tf32x3 tensor-core projections, cp.async staged ------
__global__ __launch_bounds__(128) void k1_proj(
    const float* __restrict__ u,
    const float* __restrict__ bb, const float* __restrict__ bc,
    const float* __restrict__ bd)
{
    __shared__ float  sUraw[2][64 * 36];   // raw u tile, row stride 36
    __shared__ float2 sW[2][40 * 36];      // W hi/lo pairs, row stride 36
    const int tid = threadIdx.x;
    const int w = tid >> 5, lane = tid & 31;
    const int g = lane >> 2, t = lane & 3;
    const int row0 = blockIdx.x * 64;
    const int wrow = w * 16;

    const unsigned su0 = s2u(&sUraw[0][0]);
    const unsigned sw0 = s2u(&sW[0][0]);

    auto issueK = [&](int bi, int kc) {
        // u: 512 float4, 4 per thread
        unsigned du = su0 + bi * (64 * 36) * 4;
#pragma unroll
        for (int j = 0; j < 4; j++) {
            int idx = tid + 128 * j;
            int r = idx >> 3, c4 = idx & 7;
            CP16(du + (r * 36 + c4 * 4) * 4,
                 u + (size_t)(row0 + r) * DD + kc * 32 + c4 * 4);
        }
        // W: 640 float4 (=1280 float2), 5 per thread
        unsigned dw = sw0 + bi * (40 * 36) * 8;
#pragma unroll
        for (int j = 0; j < 5; j++) {
            int idx = tid + 128 * j;
            int r = idx >> 4, q = idx & 15;
            CP16(dw + (r * 36 + q * 2) * 8, &g_Wp[r * 2048 + kc * 32 + q * 2]);
        }
    };

    float acc[5][4];
#pragma unroll
    for (int n = 0; n < 5; n++)
#pragma unroll
        for (int m = 0; m < 4; m++) acc[n][m] = 0.f;

    issueK(0, 0); CPCOMMIT();
    issueK(1, 1); CPCOMMIT();

    for (int kc = 0; kc < 64; kc++) {
        CPWAIT1();
        __syncthreads();
        const int bi = kc & 1;
        const float*  Ub = &sUraw[bi][0];
        const float2* Wb2 = &sW[bi][0];
#pragma unroll
        for (int ks = 0; ks < 4; ks++) {
            int k = ks * 8;
            float a0 = Ub[(wrow + g) * 36 + k + t];
            float a1 = Ub[(wrow + g + 8) * 36 + k + t];
            float a2 = Ub[(wrow + g) * 36 + k + t + 4];
            float a3 = Ub[(wrow + g + 8) * 36 + k + t + 4];
            unsigned ah0 = tf32b(a0), ah1 = tf32b(a1), ah2 = tf32b(a2), ah3 = tf32b(a3);
            unsigned al0 = tf32b(a0 - __uint_as_float(ah0));
            unsigned al1 = tf32b(a1 - __uint_as_float(ah1));
            unsigned al2 = tf32b(a2 - __uint_as_float(ah2));
            unsigned al3 = tf32b(a3 - __uint_as_float(ah3));
#pragma unroll
            for (int nt = 0; nt < 5; nt++) {
                float2 b0p = Wb2[(nt * 8 + g) * 36 + k + t];
                float2 b1p = Wb2[(nt * 8 + g) * 36 + k + t + 4];
                unsigned bh0 = __float_as_uint(b0p.x), bl0 = __float_as_uint(b0p.y);
                unsigned bh1 = __float_as_uint(b1p.x), bl1 = __float_as_uint(b1p.y);
                mma8(acc[nt], ah0, ah1, ah2, ah3, bh0, bh1);
                mma8(acc[nt], ah0, ah1, ah2, ah3, bl0, bl1);
                mma8(acc[nt], al0, al1, al2, al3, bh0, bh1);
            }
        }
        __syncthreads();
        if (kc + 2 < 64) issueK(bi, kc + 2);
        CPCOMMIT();
    }
    // epilogue: c0:(g,2t) c1:(g,2t+1) c2:(g+8,2t) c3:(g+8,2t+1)
    const int rlo = row0 + wrow + g, rhi = rlo + 8;
#pragma unroll
    for (int nt = 0; nt < 5; nt++) {
#pragma unroll
        for (int m = 0; m < 4; m++) {
            int row = (m & 2) ? rhi : rlo;
            int col = nt * 8 + 2 * t + (m & 1);
            float v = acc[nt][m];
            if (col < 16)       g_Bt[row * NN + col] = v + bb[col];
            else if (col < 32)  g_Ct[row * NN + col - 16] = v + bc[col - 16];
            else if (col == 32) g_Dt[row] = v + bd[0];
            else if (col == 33) g_delta[row] = 1.f / (1.f + __expf(-v));
        }
    }
}

// ---------------- K2: batched expm (PS deg-9, 1 squaring, 5 matmuls) -------
#define C3f 1.6666667e-1f
#define C4f 4.1666668e-2f
#define C5f 8.3333333e-3f
#define C6f 1.3888889e-3f
#define C7f 1.9841270e-4f
#define C8f 2.4801587e-5f
#define C9f 2.7557319e-6f

__device__ __forceinline__ void mm16(const float* __restrict__ A,
                                     const float* __restrict__ Bm,
                                     int i0, int j0, float c[4][4])
{
#pragma unroll
    for (int r = 0; r < 4; r++)
#pragma unroll
        for (int q = 0; q < 4; q++) c[r][q] = 0.f;
#pragma unroll
    for (int k = 0; k < 16; k++) {
        float b0 = Bm[k * 17 + j0 + 0];
        float b1 = Bm[k * 17 + j0 + 1];
        float b2 = Bm[k * 17 + j0 + 2];
        float b3 = Bm[k * 17 + j0 + 3];
#pragma unroll
        for (int r = 0; r < 4; r++) {
            float a = A[(i0 + r) * 17 + k];
            c[r][0] = fmaf(a, b0, c[r][0]);
            c[r][1] = fmaf(a, b1, c[r][1]);
            c[r][2] = fmaf(a, b2, c[r][2]);
            c[r][3] = fmaf(a, b3, c[r][3]);
        }
    }
}

__global__ __launch_bounds__(128) void k2_expm(const float* __restrict__ Ag)
{
    __shared__ float sm[8 * 1360];
    const int tid = threadIdx.x;
    const int mat = tid >> 4, q = tid & 15;
    const int i0 = (q >> 2) * 4, j0 = (q & 3) * 4;
    const int id0 = blockIdx.x * 8 + mat;
    const int t = id0 & (LL - 1);
    const float sd = 0.5f * g_delta[id0];

    float* Mb = sm + mat * 1360;
    float* M2b = Mb + 272;
    float* M3b = Mb + 544;
    float* T1 = Mb + 816;
    float* T2 = Mb + 1088;

    const float4* Ar = reinterpret_cast<const float4*>(Ag + (size_t)t * 256 + q * 16);
    float4 v0 = Ar[0], v1 = Ar[1], v2 = Ar[2], v3 = Ar[3];
    float* dst = Mb + q * 17;
    dst[0] = v0.x * sd;  dst[1] = v0.y * sd;  dst[2] = v0.z * sd;  dst[3] = v0.w * sd;
    dst[4] = v1.x * sd;  dst[5] = v1.y * sd;  dst[6] = v1.z * sd;  dst[7] = v1.w * sd;
    dst[8] = v2.x * sd;  dst[9] = v2.y * sd;  dst[10] = v2.z * sd; dst[11] = v2.w * sd;
    dst[12] = v3.x * sd; dst[13] = v3.y * sd; dst[14] = v3.z * sd; dst[15] = v3.w * sd;
    __syncwarp();

    float c[4][4];
    mm16(Mb, Mb, i0, j0, c);                 // M2
#pragma unroll
    for (int r = 0; r < 4; r++)
#pragma unroll
        for (int cc = 0; cc < 4; cc++) M2b[(i0 + r) * 17 + j0 + cc] = c[r][cc];
    __syncwarp();
    mm16(M2b, Mb, i0, j0, c);                // M3
#pragma unroll
    for (int r = 0; r < 4; r++)
#pragma unroll
        for (int cc = 0; cc < 4; cc++) M3b[(i0 + r) * 17 + j0 + cc] = c[r][cc];
    __syncwarp();
#pragma unroll
    for (int r = 0; r < 4; r++)              // T1 = b2
#pragma unroll
        for (int cc = 0; cc < 4; cc++) {
            int idx = (i0 + r) * 17 + j0 + cc;
            float val = C7f * Mb[idx] + C8f * M2b[idx] + C9f * M3b[idx];
            if (i0 + r == j0 + cc) val += C6f;
            T1[idx] = val;
        }
    __syncwarp();
    mm16(M3b, T1, i0, j0, c);                // T2 = M3*b2 + b1
#pragma unroll
    for (int r = 0; r < 4; r++)
#pragma unroll
        for (int cc = 0; cc < 4; cc++) {
            int idx = (i0 + r) * 17 + j0 + cc;
            float val = c[r][cc] + C4f * Mb[idx] + C5f * M2b[idx];
            if (i0 + r == j0 + cc) val += C3f;
            T2[idx] = val;
        }
    __syncwarp();
    mm16(M3b, T2, i0, j0, c);                // T1 = T9(M/2)
#pragma unroll
    for (int r = 0; r < 4; r++)
#pragma unroll
        for (int cc = 0; cc < 4; cc++) {
            int idx = (i0 + r) * 17 + j0 + cc;
            float val = c[r][cc] + Mb[idx] + 0.5f * M2b[idx];
            if (i0 + r == j0 + cc) val += 1.f;
            T1[idx] = val;
        }
    __syncwarp();
    mm16(T1, T1, i0, j0, c);                 // single squaring -> Ad
    size_t ob = (size_t)id0 * 256;
#pragma unroll
    for (int r = 0; r < 4; r++)
        *reinterpret_cast<float4*>(g_Ad + ob + (i0 + r) * 16 + j0) =
            make_float4(c[r][0], c[r][1], c[r][2], c[r][3]);
}

// ---------------- scan1: per-chunk (P,q), cp.async pipelined ----------------
#define S1W 1248
__global__ __launch_bounds__(128) void k_scan1()
{
    __shared__ float sm[4 * S1W];
    const int warp = threadIdx.x >> 5, lane = threadIdx.x & 31;
    const int chunk = blockIdx.x * 4 + warp;
    float* base = sm + warp * S1W;
    float* P0 = base;
    float* P1 = base + 272;
    float* qb = base + 544;
    float* AdB = base + 576;

    for (int i = lane; i < 272; i += 32) {
        int r = i / 17, col = i % 17;
        P0[i] = (col < 16 && r == col) ? 1.f : 0.f;
    }
    if (lane < 16) qb[lane] = 0.f;

    const unsigned adu = s2u(AdB);
    const size_t row0 = (size_t)chunk * CS;

    auto issue = [&](int bi, size_t rr) {
        unsigned d = adu + bi * 336 * 4;
#pragma unroll
        for (int j = 0; j < 2; j++) {
            int f = lane + 32 * j;
            int r = f >> 2, c = (f & 3) << 2;
            CP16(d + (r * 20 + c) * 4, g_Ad + rr * 256 + f * 4);
        }
        if (lane < 4) CP16(d + (320 + lane * 4) * 4, g_Bt + rr * 16 + lane * 4);
    };

    issue(0, row0); CPCOMMIT();
    issue(1, row0 + 1); CPCOMMIT();

    const int i0 = (lane >> 2) * 2, j0 = (lane & 3) * 4;
    float* Pc = P0; float* Pn = P1;
    int qc = 0;
    for (int tt = 0; tt < CS; tt++) {
        CPWAIT1();
        __syncwarp();
        const float* Ab = AdB + (tt & 1) * 336;
        const float* Btb = Ab + 320;
        float c0[4] = {0, 0, 0, 0}, c1[4] = {0, 0, 0, 0};
#pragma unroll
        for (int k = 0; k < 16; k++) {
            float a0 = Ab[i0 * 20 + k], a1 = Ab[(i0 + 1) * 20 + k];
            float b0 = Pc[k * 17 + j0 + 0];
            float b1 = Pc[k * 17 + j0 + 1];
            float b2 = Pc[k * 17 + j0 + 2];
            float b3 = Pc[k * 17 + j0 + 3];
            c0[0] = fmaf(a0, b0, c0[0]); c0[1] = fmaf(a0, b1, c0[1]);
            c0[2] = fmaf(a0, b2, c0[2]); c0[3] = fmaf(a0, b3, c0[3]);
            c1[0] = fmaf(a1, b0, c1[0]); c1[1] = fmaf(a1, b1, c1[1]);
            c1[2] = fmaf(a1, b2, c1[2]); c1[3] = fmaf(a1, b3, c1[3]);
        }
#pragma unroll
        for (int m = 0; m < 4; m++) {
            Pn[i0 * 17 + j0 + m] = c0[m];
            Pn[(i0 + 1) * 17 + j0 + m] = c1[m];
        }
        if (lane < 16) {
            float sn = Btb[lane];
            const float* ar = Ab + lane * 20;
            const float* qo = qb + qc * 16;
#pragma unroll
            for (int k = 0; k < 16; k++) sn = fmaf(ar[k], qo[k], sn);
            qb[(qc ^ 1) * 16 + lane] = sn;
        }
        __syncwarp();
        if (tt + 2 < CS) issue(tt & 1, row0 + tt + 2);
        CPCOMMIT();
        float* tmp = Pc; Pc = Pn; Pn = tmp;
        qc ^= 1;
    }
#pragma unroll
    for (int m = 0; m < 4; m++) {
        g_cP[chunk * 256 + i0 * 16 + j0 + m] = Pc[i0 * 17 + j0 + m];
        g_cP[chunk * 256 + (i0 + 1) * 16 + j0 + m] = Pc[(i0 + 1) * 17 + j0 + m];
    }
    if (lane < 16) g_cq[chunk * 16 + lane] = qb[qc * 16 + lane];
}

// ---------------- scan2: bulk-stage 32 chunks to smem, warp0 scans ----------
__global__ __launch_bounds__(512) void k_scan2()
{
    __shared__ float Ps[32][272];
    __shared__ float qs[32][16];
    const int tid = threadIdx.x;
    const int b = blockIdx.x;
    const int lane = tid & 31;
    float s = 0.f;

    for (int h = 0; h < 2; h++) {
        const int cbase = b * CPB + h * 32;
        for (int i = tid; i < 32 * 256; i += 512) {
            int ch = i >> 8, f = i & 255;
            int r = f >> 4, cc = f & 15;
            Ps[ch][r * 17 + cc] = g_cP[(size_t)(cbase + ch) * 256 + f];
        }
        {
            int ch = tid >> 4;
            if (ch < 32) qs[ch][tid & 15] = g_cq[(cbase + ch) * 16 + (tid & 15)];
        }
        __syncthreads();
        if (tid < 32 && lane < 16) {
            for (int ci = 0; ci < 32; ci++) {
                g_cS[(cbase + ci) * 16 + lane] = s;
                const float* prow = &Ps[ci][lane * 17];
                float a0 = 0.f, a1 = 0.f, a2 = 0.f, a3 = 0.f;
#pragma unroll
                for (int k = 0; k < 4; k++) {
                    a0 = fmaf(prow[k],      __shfl_sync(0xffffu, s, k,      16), a0);
                    a1 = fmaf(prow[k + 4],  __shfl_sync(0xffffu, s, k + 4,  16), a1);
                    a2 = fmaf(prow[k + 8],  __shfl_sync(0xffffu, s, k + 8,  16), a2);
                    a3 = fmaf(prow[k + 12], __shfl_sync(0xffffu, s, k + 12, 16), a3);
                }
                s = ((a0 + a1) + (a2 + a3)) + qs[ci][lane];
            }
        }
        __syncthreads();
    }
}

// ---------------- scan3: replay + output, cp.async pipelined ----------------
#define S3C 356
#define S3B (2*S3C)
#define S3W (2*S3B)
__global__ __launch_bounds__(128) void k_scan3(float* __restrict__ y)
{
    __shared__ float sm[4 * S3W];
    const int warp = threadIdx.x >> 5, lane = threadIdx.x & 31;
    const int half = lane >> 4, l = lane & 15;
    const int chunk0 = blockIdx.x * 8 + warp * 2;
    float* base = sm + warp * S3W;
    const unsigned bu = s2u(base);
    const size_t r0 = (size_t)chunk0 * CS;

    auto issue = [&](int bi, int tt) {
        unsigned d = bu + bi * S3B * 4;
        size_t ra = r0 + tt, rb = r0 + CS + tt;
#pragma unroll
        for (int j = 0; j < 2; j++) {
            int f = lane + 32 * j;
            int r = f >> 2, c = (f & 3) << 2;
            unsigned off = (r * 20 + c) * 4;
            CP16(d + off,           g_Ad + ra * 256 + f * 4);
            CP16(d + S3C * 4 + off, g_Ad + rb * 256 + f * 4);
        }
        if (lane < 4)       CP16(d + (320 + lane * 4) * 4,              g_Bt + ra * 16 + lane * 4);
        else if (lane < 8)  CP16(d + (S3C + 320 + (lane - 4) * 4) * 4,  g_Bt + rb * 16 + (lane - 4) * 4);
        else if (lane < 12) CP16(d + (336 + (lane - 8) * 4) * 4,        g_Ct + ra * 16 + (lane - 8) * 4);
        else if (lane < 16) CP16(d + (S3C + 336 + (lane - 12) * 4) * 4, g_Ct + rb * 16 + (lane - 12) * 4);
        else if (lane == 16) CP4(d + 352 * 4,         g_Dt + ra);
        else if (lane == 17) CP4(d + (S3C + 352) * 4, g_Dt + rb);
    };

    issue(0, 0); CPCOMMIT();
    issue(1, 1); CPCOMMIT();

    float s = g_cS[(chunk0 + half) * 16 + l];
    size_t row = r0 + half * CS;
    for (int tt = 0; tt < CS; tt++, row++) {
        CPWAIT1();
        __syncwarp();
        const float* cb = base + (tt & 1) * S3B + half * S3C;
        float4 a0 = *reinterpret_cast<const float4*>(cb + l * 20);
        float4 a1 = *reinterpret_cast<const float4*>(cb + l * 20 + 4);
        float4 a2 = *reinterpret_cast<const float4*>(cb + l * 20 + 8);
        float4 a3 = *reinterpret_cast<const float4*>(cb + l * 20 + 12);
        float btv = cb[320 + l], ctv = cb[336 + l], dtv = cb[352];

        float x0 = 0.f, x1 = 0.f, x2 = 0.f, x3 = 0.f;
        x0 = fmaf(a0.x, __shfl_sync(0xffffffffu, s, 0, 16), x0);
        x0 = fmaf(a0.y, __shfl_sync(0xffffffffu, s, 1, 16), x0);
        x0 = fmaf(a0.z, __shfl_sync(0xffffffffu, s, 2, 16), x0);
        x0 = fmaf(a0.w, __shfl_sync(0xffffffffu, s, 3, 16), x0);
        x1 = fmaf(a1.x, __shfl_sync(0xffffffffu, s, 4, 16), x1);
        x1 = fmaf(a1.y, __shfl_sync(0xffffffffu, s, 5, 16), x1);
        x1 = fmaf(a1.z, __shfl_sync(0xffffffffu, s, 6, 16), x1);
        x1 = fmaf(a1.w, __shfl_sync(0xffffffffu, s, 7, 16), x1);
        x2 = fmaf(a2.x, __shfl_sync(0xffffffffu, s, 8, 16), x2);
        x2 = fmaf(a2.y, __shfl_sync(0xffffffffu, s, 9, 16), x2);
        x2 = fmaf(a2.z, __shfl_sync(0xffffffffu, s, 10, 16), x2);
        x2 = fmaf(a2.w, __shfl_sync(0xffffffffu, s, 11, 16), x2);
        x3 = fmaf(a3.x, __shfl_sync(0xffffffffu, s, 12, 16), x3);
        x3 = fmaf(a3.y, __shfl_sync(0xffffffffu, s, 13, 16), x3);
        x3 = fmaf(a3.z, __shfl_sync(0xffffffffu, s, 14, 16), x3);
        x3 = fmaf(a3.w, __shfl_sync(0xffffffffu, s, 15, 16), x3);
        s = ((x0 + x1) + (x2 + x3)) + btv;
        float v = ctv * s;
#pragma unroll
        for (int o = 8; o > 0; o >>= 1) v += __shfl_xor_sync(0xffffffffu, v, o, 16);
        if (l == 0) y[row] = v + dtv;
        __syncwarp();
        if (tt + 2 < CS) issue(tt & 1, tt + 2);
        CPCOMMIT();
    }
}

extern "C" void kernel_launch(void* const* d_in, const int* in_sizes, int n_in,
                              void* d_out, int out_size)
{
    const float* u  = (const float*)d_in[0];
    const float* A  = (const float*)d_in[1];
    const float* dp = (const float*)d_in[2];
    const float* Wb = (const float*)d_in[3];
    const float* bb = (const float*)d_in[4];
    const float* Wc = (const float*)d_in[5];
    const float* bc = (const float*)d_in[6];
    const float* Wd = (const float*)d_in[7];
    const float* bd = (const float*)d_in[8];
    float* y = (float*)d_out;

    k0_wsplit<<<(40 * 2048) / 256, 256>>>(Wb, Wc, Wd, dp);
    k1_proj<<<ROWS / 64, 128>>>(u, bb, bc, bd);
    k2_expm<<<ROWS / 8, 128>>>(A);
    k_scan1<<<NCHUNK / 4, 128>>>();
    k_scan2<<<BB, 512>>>();
    k_scan3<<<NCHUNK / 8, 128>>>(y);
}